// round 6
// baseline (speedup 1.0000x reference)
#include <cuda_runtime.h>
#include <math.h>
#include <stdint.h>

#define B_ 4
#define T_ 2048
#define D_ 1024
#define H_ 16
#define P_ 64
#define M_ (B_*T_)   // 8192

// Scratch (allocation-free rule: __device__ globals)
__device__ float g_q[(size_t)B_*H_*T_*P_];
__device__ float g_k[(size_t)B_*H_*T_*P_];
__device__ float g_v[(size_t)B_*H_*T_*P_];   // layout [B,H,P,T] (transposed V!)
__device__ float g_y[(size_t)M_*D_];
__device__ float g_xr[(size_t)M_*D_];        // x rounded to tf32
__device__ float g_wt[(size_t)4*1024*1024];  // W^T (n-major), tf32-rounded

// ---------------------------------------------------------------------------
// Helpers
// ---------------------------------------------------------------------------
__device__ __forceinline__ uint32_t f2tf32(float x) {
    uint32_t r;
    asm("cvt.rna.tf32.f32 %0, %1;" : "=r"(r) : "f"(x));
    return r;
}
__device__ __forceinline__ float f2tf32f(float x) {
    return __uint_as_float(f2tf32(x));
}
__device__ __forceinline__ uint32_t smem_u32(const void* p) {
    return (uint32_t)__cvta_generic_to_shared(p);
}
__device__ __forceinline__ void ldsm4(uint32_t& r0, uint32_t& r1,
                                      uint32_t& r2, uint32_t& r3, uint32_t addr) {
    asm volatile("ldmatrix.sync.aligned.m8n8.x4.shared.b16 {%0,%1,%2,%3}, [%4];"
                 : "=r"(r0), "=r"(r1), "=r"(r2), "=r"(r3) : "r"(addr));
}
__device__ __forceinline__ void mma_tf32(float c[4], const uint32_t a[4],
                                         uint32_t b0, uint32_t b1) {
    asm volatile(
        "mma.sync.aligned.m16n8k8.row.col.f32.tf32.tf32.f32 "
        "{%0,%1,%2,%3}, {%4,%5,%6,%7}, {%8,%9}, {%0,%1,%2,%3};"
        : "+f"(c[0]), "+f"(c[1]), "+f"(c[2]), "+f"(c[3])
        : "r"(a[0]), "r"(a[1]), "r"(a[2]), "r"(a[3]), "r"(b0), "r"(b1));
}
__device__ __forceinline__ void cp16(uint32_t dst, const void* src) {
    asm volatile("cp.async.cg.shared.global [%0], [%1], 16;"
                 :: "r"(dst), "l"(src));
}
__device__ __forceinline__ void cp_commit() {
    asm volatile("cp.async.commit_group;");
}
__device__ __forceinline__ void cp_wait0() {
    asm volatile("cp.async.wait_group 0;" ::: "memory");
}
__device__ __forceinline__ void cp_wait1() {
    asm volatile("cp.async.wait_group 1;" ::: "memory");
}
__device__ __forceinline__ void sts64(uint32_t dst, uint32_t a, uint32_t b) {
    asm volatile("st.shared.v2.b32 [%0], {%1,%2};" :: "r"(dst), "r"(a), "r"(b));
}

// ---------------------------------------------------------------------------
// Prep kernels: round x; round+transpose weights (Wt[n][k]).
// ---------------------------------------------------------------------------
__global__ void prep_x(const float* __restrict__ x)
{
    int i4 = blockIdx.x * blockDim.x + threadIdx.x;
    float4 v = ((const float4*)x)[i4];
    ((float4*)g_xr)[i4] = make_float4(f2tf32f(v.x), f2tf32f(v.y),
                                      f2tf32f(v.z), f2tf32f(v.w));
}

__global__ void prep_wt(const float* __restrict__ wq,
                        const float* __restrict__ wk,
                        const float* __restrict__ wv,
                        const float* __restrict__ wo)
{
    __shared__ float tile[32][33];
    const int z = blockIdx.z;
    const float* W = (z == 0) ? wq : (z == 1) ? wk : (z == 2) ? wv : wo;
    const int k0 = blockIdx.y * 32;
    const int n0 = blockIdx.x * 32;
    const int t = threadIdx.x;
    const int r = t >> 3;
    const int c4 = (t & 7) * 4;

    float4 v = *(const float4*)&W[(size_t)(k0 + r) * 1024 + n0 + c4];
    tile[r][c4 + 0] = f2tf32f(v.x);
    tile[r][c4 + 1] = f2tf32f(v.y);
    tile[r][c4 + 2] = f2tf32f(v.z);
    tile[r][c4 + 3] = f2tf32f(v.w);
    __syncthreads();
    // Wt[n0+r][k0+c4..+3] = W[k0+c4..+3][n0+r]
    float4 o = make_float4(tile[c4 + 0][r], tile[c4 + 1][r],
                           tile[c4 + 2][r], tile[c4 + 3][r]);
    *(float4*)&g_wt[(size_t)z * 1048576 + (size_t)(n0 + r) * 1024 + k0 + c4] = o;
}

// ---------------------------------------------------------------------------
// tf32 tensor-core GEMM: C[M,1024] = A[M,1024] * W[1024,1024]
// Block tile 256x128, K-tile 32, 3-stage cp.async pipeline.
// 512 threads = 16 warps (4M x 4N), warp 64x32.
// A and B^T both in pad-36 smem rows (144B = odd*16B -> ldmatrix conflict-free).
// MODE 0: A = g_xr, z selects Wt and output (q/k: [B,H,T,P]; v: [B,H,P,T]).
// MODE 1: A = g_y, W = Wo^T, C = d_out plain f32.
// ---------------------------------------------------------------------------
#define GLD 36
#define AS_F (256*GLD)            // 9216 floats
#define BS_F (128*GLD)            // 4608 floats
#define STAGE_F (AS_F + BS_F)     // 13824
#define GEMM_SMEM_BYTES (3*STAGE_F*4)   // 165888

template <int MODE>
__global__ __launch_bounds__(512, 1)
void gemm_tc(float* __restrict__ outp)
{
    extern __shared__ float sm_g[];
    const int m0 = blockIdx.y * 256;
    const int n0 = blockIdx.x * 128;
    const int z  = (MODE == 0) ? blockIdx.z : 3;

    const float* Ap = (MODE == 0) ? g_xr : g_y;
    const float* Wt = g_wt + (size_t)z * 1048576;
    float* Cq = nullptr;
    if (MODE == 0) Cq = (z == 0) ? g_q : ((z == 1) ? g_k : g_v);

    const int tid  = threadIdx.x;
    const int lane = tid & 31;
    const int warp = tid >> 5;
    const int wm = (warp >> 2) * 64;
    const int wn = (warp & 3) * 32;
    const int gid = lane >> 2;
    const int tig = lane & 3;

    const int aRow    = (lane < 16) ? lane : (lane - 16);
    const int aColOff = (lane < 16) ? 0 : 4;
    const int rowRel  = ((lane >> 4) << 3) + (lane & 7);
    const int hb      = (lane >> 3) & 1;

    const uint32_t smBase = smem_u32(sm_g);
    // per-lane fragment byte offsets within a stage
    const uint32_t aOff = (uint32_t)((wm + aRow) * GLD + aColOff) * 4u;
    uint32_t bOff[2];
#pragma unroll
    for (int nfp = 0; nfp < 2; nfp++)
        bOff[nfp] = (uint32_t)((wn + nfp * 16 + rowRel) * GLD + hb * 4) * 4u
                    + (uint32_t)AS_F * 4u;

    float acc[4][4][4];
#pragma unroll
    for (int mf = 0; mf < 4; mf++)
#pragma unroll
        for (int nf = 0; nf < 4; nf++)
#pragma unroll
            for (int i = 0; i < 4; i++) acc[mf][nf][i] = 0.f;

    auto cpStage = [&](int kt, int s) {
        uint32_t As = smBase + (uint32_t)(s * STAGE_F) * 4u;
        uint32_t Bs = As + (uint32_t)AS_F * 4u;
#pragma unroll
        for (int r = 0; r < 4; r++) {
            int lin  = tid + r * 512;
            int arow = lin >> 3;
            int ac4  = (lin & 7) * 4;
            cp16(As + (uint32_t)(arow * GLD + ac4) * 4u,
                 Ap + (size_t)(m0 + arow) * 1024 + kt * 32 + ac4);
        }
#pragma unroll
        for (int r = 0; r < 2; r++) {
            int lin  = tid + r * 512;
            int brow = lin >> 3;
            int bc4  = (lin & 7) * 4;
            cp16(Bs + (uint32_t)(brow * GLD + bc4) * 4u,
                 Wt + (size_t)(n0 + brow) * 1024 + kt * 32 + bc4);
        }
        cp_commit();
    };

    cpStage(0, 0);
    cpStage(1, 1);

    for (int kt = 0; kt < 32; kt++) {
        if (kt < 31) cp_wait1(); else cp_wait0();
        __syncthreads();
        if (kt + 2 < 32) cpStage(kt + 2, (kt + 2) % 3);

        const uint32_t stB = smBase + (uint32_t)((kt % 3) * STAGE_F) * 4u;
        const uint32_t aB  = stB + aOff;
#pragma unroll
        for (int kf = 0; kf < 4; kf++) {
            uint32_t a[4][4];
#pragma unroll
            for (int mf = 0; mf < 4; mf++)
                ldsm4(a[mf][0], a[mf][1], a[mf][2], a[mf][3],
                      aB + (uint32_t)(mf * 16 * GLD + kf * 8) * 4u);
            uint32_t b[4][2];
            ldsm4(b[0][0], b[0][1], b[1][0], b[1][1],
                  stB + bOff[0] + (uint32_t)(kf * 32));
            ldsm4(b[2][0], b[2][1], b[3][0], b[3][1],
                  stB + bOff[1] + (uint32_t)(kf * 32));
#pragma unroll
            for (int mf = 0; mf < 4; mf++)
#pragma unroll
                for (int nf = 0; nf < 4; nf++)
                    mma_tf32(acc[mf][nf], a[mf], b[nf][0], b[nf][1]);
        }
    }

    // Epilogue
#pragma unroll
    for (int mf = 0; mf < 4; mf++) {
#pragma unroll
        for (int nf = 0; nf < 4; nf++) {
            int row = m0 + wm + mf * 16 + gid;
            int col = n0 + wn + nf * 8 + tig * 2;
#pragma unroll
            for (int half = 0; half < 2; half++) {
                int rr = row + half * 8;
                float v0 = acc[mf][nf][half * 2];
                float v1 = acc[mf][nf][half * 2 + 1];
                if (MODE == 0) {
                    int b = rr >> 11;
                    int t = rr & 2047;
                    int h = col >> 6;
                    int p = col & 63;
                    if (z == 2) {
                        // V transposed: [B,H,P,T]
                        size_t o = (((size_t)(b * H_ + h) * P_ + p) * T_ + t);
                        Cq[o]      = f2tf32f(v0);
                        Cq[o + T_] = f2tf32f(v1);
                    } else {
                        *(float2*)&Cq[(((size_t)(b * H_ + h) * T_ + t) * P_ + p)] =
                            make_float2(f2tf32f(v0), f2tf32f(v1));
                    }
                } else {
                    *(float2*)&outp[(size_t)rr * 1024 + col] = make_float2(v0, v1);
                }
            }
        }
    }
}

// ---------------------------------------------------------------------------
// tf32 tensor-core flash attention, causal. 256 thr = 8 warps, 128 q-rows,
// kv tiles of 64. Q/K/V all via cp.async (V pre-transposed [d][t] -> direct
// coalesced fill of the swizzled Vt smem layout). K b-frags via ldmatrix on
// natural [kv][d] pad-68 layout (conflict-free).
// ---------------------------------------------------------------------------
#define LDQ 68
#define LDK 68
#define LDP 68
#define KS_OFF (128*LDQ)              // 8704
#define PS_OFF (KS_OFF + 64*LDK)      // 13056
#define VT_OFF (PS_OFF + 128*LDP)     // 21760 (x4: 87040, 256B aligned)
#define ATTN_SMEM_FLOATS (VT_OFF + 64*64)
#define ATTN_SMEM_BYTES  (ATTN_SMEM_FLOATS*4)

__global__ __launch_bounds__(256, 1)
void attn_tc()
{
    extern __shared__ float sm[];

    const int bh = blockIdx.y;
    const int b  = bh >> 4;
    const int h  = bh & 15;
    const int qt = (int)gridDim.x - 1 - (int)blockIdx.x;  // heavy blocks first
    const int q0 = qt * 128;

    const size_t base = (size_t)bh * T_ * P_;
    const float* Qp  = g_q + base;
    const float* Kp  = g_k + base;
    const float* VpT = g_v + base;   // [d][t] per (b,h)

    const int tid  = threadIdx.x;
    const int lane = tid & 31;
    const int warp = tid >> 5;
    const int gid  = lane >> 2;
    const int tig  = lane & 3;
    const int aRow    = (lane < 16) ? lane : (lane - 16);
    const int aColOff = (lane < 16) ? 0 : 4;

    const uint32_t smBase = smem_u32(sm);
    const uint32_t QsB = smBase;
    const uint32_t KsB = smBase + KS_OFF * 4;
    const uint32_t PsB = smBase + PS_OFF * 4;
    const uint32_t VtB = smBase + VT_OFF * 4;

    // b-fragment lane constants
    const int rowRel = ((lane >> 4) << 3) + (lane & 7);
    const uint32_t hb = (lane >> 3) & 1;
    uint32_t bK[4], bV[4];
#pragma unroll
    for (int nfp = 0; nfp < 4; nfp++) {
        int row = nfp * 16 + rowRel;
        bK[nfp] = KsB + (uint32_t)(row * LDK + (int)hb * 4) * 4u;
        bV[nfp] = (uint32_t)(row * 256 + 16 * (row & 7)) ^ (hb << 4);
    }

    // Load Q tile (128x64) via cp.async
#pragma unroll
    for (int r = 0; r < 8; r++) {
        int it = tid + r * 256;
        int rw = it >> 4;
        int c4 = (it & 15) * 4;
        cp16(QsB + (uint32_t)(rw * LDQ + c4) * 4u,
             Qp + (size_t)(q0 + rw) * 64 + c4);
    }
    cp_commit();

    float accO[8][4];
#pragma unroll
    for (int nf = 0; nf < 8; nf++)
#pragma unroll
        for (int i = 0; i < 4; i++) accO[nf][i] = 0.f;
    float mr0 = -INFINITY, mr1 = -INFINITY, l0 = 0.f, l1 = 0.f;

    const float sc = 0.18033688011112042f;   // 0.125 * log2(e)
    const int ntiles = 2 * qt + 2;

    for (int jt = 0; jt < ntiles; jt++) {
        const int j0 = jt * 64;
        __syncthreads();   // prior compute done with Ks/Vt
        // K tile (64 x 64) cp.async
#pragma unroll
        for (int r = 0; r < 4; r++) {
            int it = tid + r * 256;
            int rw = it >> 4;
            int c4 = (it & 15) * 4;
            cp16(KsB + (uint32_t)(rw * LDK + c4) * 4u,
                 Kp + (size_t)(j0 + rw) * 64 + c4);
        }
        // V tile: rows d=0..63, 16B chunks along t -> swizzled Vt[d][kv]
#pragma unroll
        for (int r = 0; r < 4; r++) {
            int u   = tid + r * 256;
            int d   = u >> 4;
            int kvb = u & 15;
            cp16(VtB + (uint32_t)(d * 256 + 16 * (kvb ^ (d & 7))),
                 VpT + (size_t)d * T_ + j0 + kvb * 4);
        }
        cp_commit();
        cp_wait0();
        __syncthreads();

        // ---- S = Q K^T  (warp: 16 rows x 64 cols) ----
        float c[8][4];
#pragma unroll
        for (int nf = 0; nf < 8; nf++)
#pragma unroll
            for (int i = 0; i < 4; i++) c[nf][i] = 0.f;

        const uint32_t aBaseQ = QsB + (uint32_t)((warp * 16 + aRow) * LDQ + aColOff) * 4u;
#pragma unroll
        for (int kf = 0; kf < 8; kf++) {
            uint32_t a[4];
            ldsm4(a[0], a[1], a[2], a[3], aBaseQ + (uint32_t)(kf * 8) * 4u);
#pragma unroll
            for (int nfp = 0; nfp < 4; nfp++) {
                uint32_t b0, b1, b2, b3;
                ldsm4(b0, b1, b2, b3, bK[nfp] + (uint32_t)(kf * 32));
                mma_tf32(c[2 * nfp],     a, b0, b1);
                mma_tf32(c[2 * nfp + 1], a, b2, b3);
            }
        }

        // ---- causal mask (last two tiles only) ----
        if (jt >= 2 * qt) {
            int row0 = q0 + warp * 16 + gid;
#pragma unroll
            for (int nf = 0; nf < 8; nf++) {
                int col = j0 + nf * 8 + tig * 2;
                if (col     > row0)     c[nf][0] = -INFINITY;
                if (col + 1 > row0)     c[nf][1] = -INFINITY;
                if (col     > row0 + 8) c[nf][2] = -INFINITY;
                if (col + 1 > row0 + 8) c[nf][3] = -INFINITY;
            }
        }

        // ---- online softmax ----
        float rm0 = -INFINITY, rm1 = -INFINITY;
#pragma unroll
        for (int nf = 0; nf < 8; nf++) {
            rm0 = fmaxf(rm0, fmaxf(c[nf][0], c[nf][1]));
            rm1 = fmaxf(rm1, fmaxf(c[nf][2], c[nf][3]));
        }
#pragma unroll
        for (int off = 1; off < 4; off <<= 1) {
            rm0 = fmaxf(rm0, __shfl_xor_sync(0xffffffffu, rm0, off));
            rm1 = fmaxf(rm1, __shfl_xor_sync(0xffffffffu, rm1, off));
        }
        float mn0 = fmaxf(mr0, rm0);
        float mn1 = fmaxf(mr1, rm1);
        float al0 = exp2f((mr0 - mn0) * sc);
        float al1 = exp2f((mr1 - mn1) * sc);
        float rs0 = 0.f, rs1 = 0.f;
#pragma unroll
        for (int nf = 0; nf < 8; nf++) {
            c[nf][0] = exp2f((c[nf][0] - mn0) * sc);
            c[nf][1] = exp2f((c[nf][1] - mn0) * sc);
            c[nf][2] = exp2f((c[nf][2] - mn1) * sc);
            c[nf][3] = exp2f((c[nf][3] - mn1) * sc);
            rs0 += c[nf][0] + c[nf][1];
            rs1 += c[nf][2] + c[nf][3];
        }
#pragma unroll
        for (int off = 1; off < 4; off <<= 1) {
            rs0 += __shfl_xor_sync(0xffffffffu, rs0, off);
            rs1 += __shfl_xor_sync(0xffffffffu, rs1, off);
        }
        l0 = l0 * al0 + rs0;
        l1 = l1 * al1 + rs1;
        mr0 = mn0;
        mr1 = mn1;
#pragma unroll
        for (int nf = 0; nf < 8; nf++) {
            accO[nf][0] *= al0;
            accO[nf][1] *= al0;
            accO[nf][2] *= al1;
            accO[nf][3] *= al1;
        }

        // ---- stage P (warp-local rows, packed 64-bit stores) ----
        {
            uint32_t p0 = PsB + (uint32_t)((warp * 16 + gid) * LDP + tig * 2) * 4u;
            uint32_t p1 = p0 + (uint32_t)(8 * LDP) * 4u;
#pragma unroll
            for (int nf = 0; nf < 8; nf++) {
                sts64(p0 + (uint32_t)(nf * 32), f2tf32(c[nf][0]), f2tf32(c[nf][1]));
                sts64(p1 + (uint32_t)(nf * 32), f2tf32(c[nf][2]), f2tf32(c[nf][3]));
            }
        }
        __syncwarp();

        // ---- O += P @ V (V^T in smem, ldmatrix b-frags) ----
        const uint32_t aBaseP = PsB + (uint32_t)((warp * 16 + aRow) * LDP + aColOff) * 4u;
#pragma unroll
        for (int kf = 0; kf < 8; kf++) {
            uint32_t a[4];
            ldsm4(a[0], a[1], a[2], a[3], aBaseP + (uint32_t)(kf * 8) * 4u);
#pragma unroll
            for (int nfp = 0; nfp < 4; nfp++) {
                uint32_t b0, b1, b2, b3;
                ldsm4(b0, b1, b2, b3, VtB + (bV[nfp] ^ (uint32_t)(kf << 5)));
                mma_tf32(accO[2 * nfp],     a, b0, b1);
                mma_tf32(accO[2 * nfp + 1], a, b2, b3);
            }
        }
        __syncwarp();
    }

    // ---- finalize; write tf32-rounded to g_y [B,T,H*P] ----
    float inv0 = 1.f / l0;
    float inv1 = 1.f / l1;
    int rowg = q0 + warp * 16 + gid;
    float* y0 = g_y + ((size_t)(b * T_ + rowg)) * D_ + h * 64 + tig * 2;
    float* y1 = y0 + 8 * (size_t)D_;
#pragma unroll
    for (int nf = 0; nf < 8; nf++) {
        *(float2*)&y0[nf * 8] = make_float2(f2tf32f(accO[nf][0] * inv0),
                                            f2tf32f(accO[nf][1] * inv0));
        *(float2*)&y1[nf * 8] = make_float2(f2tf32f(accO[nf][2] * inv1),
                                            f2tf32f(accO[nf][3] * inv1));
    }
}

// ---------------------------------------------------------------------------
extern "C" void kernel_launch(void* const* d_in, const int* in_sizes, int n_in,
                              void* d_out, int out_size)
{
    const float* x  = (const float*)d_in[0];
    const float* Wq = (const float*)d_in[2];
    const float* Wk = (const float*)d_in[3];
    const float* Wv = (const float*)d_in[4];
    const float* Wo = (const float*)d_in[5];
    float* out = (float*)d_out;

    cudaFuncSetAttribute(gemm_tc<0>, cudaFuncAttributeMaxDynamicSharedMemorySize,
                         GEMM_SMEM_BYTES);
    cudaFuncSetAttribute(gemm_tc<1>, cudaFuncAttributeMaxDynamicSharedMemorySize,
                         GEMM_SMEM_BYTES);
    cudaFuncSetAttribute(attn_tc, cudaFuncAttributeMaxDynamicSharedMemorySize,
                         ATTN_SMEM_BYTES);

    // Round x; round + transpose weights
    prep_x<<<8192, 256>>>(x);
    prep_wt<<<dim3(32, 32, 4), 256>>>(Wq, Wk, Wv, Wo);

    // QKV projections (V written transposed)
    gemm_tc<0><<<dim3(8, 32, 3), 512, GEMM_SMEM_BYTES>>>(nullptr);

    // Flash attention
    attn_tc<<<dim3(T_/128, B_*H_), 256, ATTN_SMEM_BYTES>>>();

    // Output projection
    gemm_tc<1><<<dim3(8, 32, 1), 512, GEMM_SMEM_BYTES>>>(out);
}

// round 7
// speedup vs baseline: 1.0985x; 1.0985x over previous
#include <cuda_runtime.h>
#include <math.h>
#include <stdint.h>

#define B_ 4
#define T_ 2048
#define D_ 1024
#define H_ 16
#define P_ 64
#define M_ (B_*T_)   // 8192

// Scratch (allocation-free rule: __device__ globals)
__device__ float g_q[(size_t)B_*H_*T_*P_];
__device__ float g_k[(size_t)B_*H_*T_*P_];
__device__ float g_v[(size_t)B_*H_*T_*P_];   // layout [B,H,P,T] (transposed V!)
__device__ float g_y[(size_t)M_*D_];
__device__ float g_xr[(size_t)M_*D_];        // x rounded to tf32
__device__ float g_wt[(size_t)4*1024*1024];  // W^T (n-major), tf32-rounded

// ---------------------------------------------------------------------------
// Helpers
// ---------------------------------------------------------------------------
__device__ __forceinline__ uint32_t f2tf32(float x) {
    uint32_t r;
    asm("cvt.rna.tf32.f32 %0, %1;" : "=r"(r) : "f"(x));
    return r;
}
__device__ __forceinline__ float f2tf32f(float x) {
    return __uint_as_float(f2tf32(x));
}
__device__ __forceinline__ uint32_t smem_u32(const void* p) {
    return (uint32_t)__cvta_generic_to_shared(p);
}
__device__ __forceinline__ void ldsm4(uint32_t& r0, uint32_t& r1,
                                      uint32_t& r2, uint32_t& r3, uint32_t addr) {
    asm volatile("ldmatrix.sync.aligned.m8n8.x4.shared.b16 {%0,%1,%2,%3}, [%4];"
                 : "=r"(r0), "=r"(r1), "=r"(r2), "=r"(r3) : "r"(addr));
}
__device__ __forceinline__ void mma_tf32(float c[4], const uint32_t a[4],
                                         uint32_t b0, uint32_t b1) {
    asm volatile(
        "mma.sync.aligned.m16n8k8.row.col.f32.tf32.tf32.f32 "
        "{%0,%1,%2,%3}, {%4,%5,%6,%7}, {%8,%9}, {%0,%1,%2,%3};"
        : "+f"(c[0]), "+f"(c[1]), "+f"(c[2]), "+f"(c[3])
        : "r"(a[0]), "r"(a[1]), "r"(a[2]), "r"(a[3]), "r"(b0), "r"(b1));
}
__device__ __forceinline__ void cp16(uint32_t dst, const void* src) {
    asm volatile("cp.async.cg.shared.global [%0], [%1], 16;"
                 :: "r"(dst), "l"(src));
}
__device__ __forceinline__ void cp_commit() {
    asm volatile("cp.async.commit_group;");
}
__device__ __forceinline__ void cp_wait0() {
    asm volatile("cp.async.wait_group 0;" ::: "memory");
}
__device__ __forceinline__ void cp_wait1() {
    asm volatile("cp.async.wait_group 1;" ::: "memory");
}
__device__ __forceinline__ void sts64(uint32_t dst, uint32_t a, uint32_t b) {
    asm volatile("st.shared.v2.b32 [%0], {%1,%2};" :: "r"(dst), "r"(a), "r"(b));
}

// ---------------------------------------------------------------------------
// Prep kernels: round x; round+transpose weights (Wt[n][k]).
// ---------------------------------------------------------------------------
__global__ void prep_x(const float* __restrict__ x)
{
    int i4 = blockIdx.x * blockDim.x + threadIdx.x;
    float4 v = ((const float4*)x)[i4];
    ((float4*)g_xr)[i4] = make_float4(f2tf32f(v.x), f2tf32f(v.y),
                                      f2tf32f(v.z), f2tf32f(v.w));
}

__global__ void prep_wt(const float* __restrict__ wq,
                        const float* __restrict__ wk,
                        const float* __restrict__ wv,
                        const float* __restrict__ wo)
{
    __shared__ float tile[32][33];
    const int z = blockIdx.z;
    const float* W = (z == 0) ? wq : (z == 1) ? wk : (z == 2) ? wv : wo;
    const int k0 = blockIdx.y * 32;
    const int n0 = blockIdx.x * 32;
    const int t = threadIdx.x;
    const int r = t >> 3;
    const int c4 = (t & 7) * 4;

    float4 v = *(const float4*)&W[(size_t)(k0 + r) * 1024 + n0 + c4];
    tile[r][c4 + 0] = f2tf32f(v.x);
    tile[r][c4 + 1] = f2tf32f(v.y);
    tile[r][c4 + 2] = f2tf32f(v.z);
    tile[r][c4 + 3] = f2tf32f(v.w);
    __syncthreads();
    float4 o = make_float4(tile[c4 + 0][r], tile[c4 + 1][r],
                           tile[c4 + 2][r], tile[c4 + 3][r]);
    *(float4*)&g_wt[(size_t)z * 1048576 + (size_t)(n0 + r) * 1024 + k0 + c4] = o;
}

// ---------------------------------------------------------------------------
// tf32 tensor-core GEMM: C[M,1024] = A[M,1024] * W[1024,1024]
// Block tile 128(M) x 256(N), K-tile 32, 3-stage cp.async pipeline.
// 256 threads = 8 warps (2M x 4N), warp tile 64x64 (4 mf x 8 nf).
// A[128][36] and B^T[256][36] pad-36 rows (144B -> ldmatrix conflict-free).
// MODE 0: A = g_xr, z selects Wt and output (q/k: [B,H,T,P]; v: [B,H,P,T]).
// MODE 1: A = g_y, W = Wo^T, C = d_out plain f32.
// ---------------------------------------------------------------------------
#define GLD 36
#define AS_F (128*GLD)            // 4608 floats
#define BS_F (256*GLD)            // 9216 floats
#define STAGE_F (AS_F + BS_F)     // 13824
#define GEMM_SMEM_BYTES (3*STAGE_F*4)   // 165888

template <int MODE>
__global__ __launch_bounds__(256, 1)
void gemm_tc(float* __restrict__ outp)
{
    extern __shared__ float sm_g[];
    const int m0 = blockIdx.y * 128;
    const int n0 = blockIdx.x * 256;
    const int z  = (MODE == 0) ? blockIdx.z : 3;

    const float* Ap = (MODE == 0) ? g_xr : g_y;
    const float* Wt = g_wt + (size_t)z * 1048576;
    float* Cq = nullptr;
    if (MODE == 0) Cq = (z == 0) ? g_q : ((z == 1) ? g_k : g_v);

    const int tid  = threadIdx.x;
    const int lane = tid & 31;
    const int warp = tid >> 5;
    const int wm = (warp >> 2) * 64;   // 2 M-warps
    const int wn = (warp & 3) * 64;    // 4 N-warps
    const int gid = lane >> 2;
    const int tig = lane & 3;

    const int aRow    = (lane < 16) ? lane : (lane - 16);
    const int aColOff = (lane < 16) ? 0 : 4;
    const int rowRel  = ((lane >> 4) << 3) + (lane & 7);
    const int hb      = (lane >> 3) & 1;

    const uint32_t smBase = smem_u32(sm_g);
    const uint32_t aOff = (uint32_t)((wm + aRow) * GLD + aColOff) * 4u;
    uint32_t bOff[4];
#pragma unroll
    for (int nfp = 0; nfp < 4; nfp++)
        bOff[nfp] = (uint32_t)((wn + nfp * 16 + rowRel) * GLD + hb * 4) * 4u
                    + (uint32_t)AS_F * 4u;

    float acc[4][8][4];
#pragma unroll
    for (int mf = 0; mf < 4; mf++)
#pragma unroll
        for (int nf = 0; nf < 8; nf++)
#pragma unroll
            for (int i = 0; i < 4; i++) acc[mf][nf][i] = 0.f;

    auto cpStage = [&](int kt, int s) {
        uint32_t As = smBase + (uint32_t)(s * STAGE_F) * 4u;
        uint32_t Bs = As + (uint32_t)AS_F * 4u;
#pragma unroll
        for (int r = 0; r < 4; r++) {
            int lin  = tid + r * 256;
            int arow = lin >> 3;
            int ac4  = (lin & 7) * 4;
            cp16(As + (uint32_t)(arow * GLD + ac4) * 4u,
                 Ap + (size_t)(m0 + arow) * 1024 + kt * 32 + ac4);
        }
#pragma unroll
        for (int r = 0; r < 8; r++) {
            int lin  = tid + r * 256;
            int brow = lin >> 3;
            int bc4  = (lin & 7) * 4;
            cp16(Bs + (uint32_t)(brow * GLD + bc4) * 4u,
                 Wt + (size_t)(n0 + brow) * 1024 + kt * 32 + bc4);
        }
        cp_commit();
    };

    cpStage(0, 0);
    cpStage(1, 1);

    for (int kt = 0; kt < 32; kt++) {
        if (kt < 31) cp_wait1(); else cp_wait0();
        __syncthreads();
        if (kt + 2 < 32) cpStage(kt + 2, (kt + 2) % 3);

        const uint32_t stB = smBase + (uint32_t)((kt % 3) * STAGE_F) * 4u;
        const uint32_t aB  = stB + aOff;
#pragma unroll
        for (int kf = 0; kf < 4; kf++) {
            uint32_t a[4][4];
#pragma unroll
            for (int mf = 0; mf < 4; mf++)
                ldsm4(a[mf][0], a[mf][1], a[mf][2], a[mf][3],
                      aB + (uint32_t)(mf * 16 * GLD + kf * 8) * 4u);
            uint32_t b[8][2];
#pragma unroll
            for (int nfp = 0; nfp < 4; nfp++)
                ldsm4(b[2*nfp][0], b[2*nfp][1], b[2*nfp+1][0], b[2*nfp+1][1],
                      stB + bOff[nfp] + (uint32_t)(kf * 32));
#pragma unroll
            for (int mf = 0; mf < 4; mf++)
#pragma unroll
                for (int nf = 0; nf < 8; nf++)
                    mma_tf32(acc[mf][nf], a[mf], b[nf][0], b[nf][1]);
        }
    }

    // Epilogue
#pragma unroll
    for (int mf = 0; mf < 4; mf++) {
#pragma unroll
        for (int nf = 0; nf < 8; nf++) {
            int row = m0 + wm + mf * 16 + gid;
            int col = n0 + wn + nf * 8 + tig * 2;
#pragma unroll
            for (int half = 0; half < 2; half++) {
                int rr = row + half * 8;
                float v0 = acc[mf][nf][half * 2];
                float v1 = acc[mf][nf][half * 2 + 1];
                if (MODE == 0) {
                    int b = rr >> 11;
                    int t = rr & 2047;
                    int h = col >> 6;
                    int p = col & 63;
                    if (z == 2) {
                        size_t o = (((size_t)(b * H_ + h) * P_ + p) * T_ + t);
                        Cq[o]      = f2tf32f(v0);
                        Cq[o + T_] = f2tf32f(v1);
                    } else {
                        *(float2*)&Cq[(((size_t)(b * H_ + h) * T_ + t) * P_ + p)] =
                            make_float2(f2tf32f(v0), f2tf32f(v1));
                    }
                } else {
                    *(float2*)&outp[(size_t)rr * 1024 + col] = make_float2(v0, v1);
                }
            }
        }
    }
}

// ---------------------------------------------------------------------------
// tf32 tensor-core flash attention, causal. 256 thr = 8 warps, 128 q-rows,
// kv tiles of 64. NOW 2 CTAs/SM (launch_bounds minBlocks=2): one CTA's
// softmax overlaps the other's mma.
// ---------------------------------------------------------------------------
#define LDQ 68
#define LDK 68
#define LDP 68
#define KS_OFF (128*LDQ)              // 8704
#define PS_OFF (KS_OFF + 64*LDK)      // 13056
#define VT_OFF (PS_OFF + 128*LDP)     // 21760 (x4: 87040, 256B aligned)
#define ATTN_SMEM_FLOATS (VT_OFF + 64*64)
#define ATTN_SMEM_BYTES  (ATTN_SMEM_FLOATS*4)   // 103424; x2 = 206848 < 228KB

__global__ __launch_bounds__(256, 2)
void attn_tc()
{
    extern __shared__ float sm[];

    const int bh = blockIdx.y;
    const int b  = bh >> 4;
    const int h  = bh & 15;
    const int qt = (int)gridDim.x - 1 - (int)blockIdx.x;  // heavy blocks first
    const int q0 = qt * 128;

    const size_t base = (size_t)bh * T_ * P_;
    const float* Qp  = g_q + base;
    const float* Kp  = g_k + base;
    const float* VpT = g_v + base;   // [d][t] per (b,h)

    const int tid  = threadIdx.x;
    const int lane = tid & 31;
    const int warp = tid >> 5;
    const int gid  = lane >> 2;
    const int tig  = lane & 3;
    const int aRow    = (lane < 16) ? lane : (lane - 16);
    const int aColOff = (lane < 16) ? 0 : 4;

    const uint32_t smBase = smem_u32(sm);
    const uint32_t QsB = smBase;
    const uint32_t KsB = smBase + KS_OFF * 4;
    const uint32_t PsB = smBase + PS_OFF * 4;
    const uint32_t VtB = smBase + VT_OFF * 4;

    const int rowRel = ((lane >> 4) << 3) + (lane & 7);
    const uint32_t hb = (lane >> 3) & 1;
    uint32_t bK[4], bV[4];
#pragma unroll
    for (int nfp = 0; nfp < 4; nfp++) {
        int row = nfp * 16 + rowRel;
        bK[nfp] = KsB + (uint32_t)(row * LDK + (int)hb * 4) * 4u;
        bV[nfp] = (uint32_t)(row * 256 + 16 * (row & 7)) ^ (hb << 4);
    }

    // Load Q tile (128x64) via cp.async
#pragma unroll
    for (int r = 0; r < 8; r++) {
        int it = tid + r * 256;
        int rw = it >> 4;
        int c4 = (it & 15) * 4;
        cp16(QsB + (uint32_t)(rw * LDQ + c4) * 4u,
             Qp + (size_t)(q0 + rw) * 64 + c4);
    }
    cp_commit();

    float accO[8][4];
#pragma unroll
    for (int nf = 0; nf < 8; nf++)
#pragma unroll
        for (int i = 0; i < 4; i++) accO[nf][i] = 0.f;
    float mr0 = -INFINITY, mr1 = -INFINITY, l0 = 0.f, l1 = 0.f;

    const float sc = 0.18033688011112042f;   // 0.125 * log2(e)
    const int ntiles = 2 * qt + 2;

    for (int jt = 0; jt < ntiles; jt++) {
        const int j0 = jt * 64;
        __syncthreads();
#pragma unroll
        for (int r = 0; r < 4; r++) {
            int it = tid + r * 256;
            int rw = it >> 4;
            int c4 = (it & 15) * 4;
            cp16(KsB + (uint32_t)(rw * LDK + c4) * 4u,
                 Kp + (size_t)(j0 + rw) * 64 + c4);
        }
#pragma unroll
        for (int r = 0; r < 4; r++) {
            int u   = tid + r * 256;
            int d   = u >> 4;
            int kvb = u & 15;
            cp16(VtB + (uint32_t)(d * 256 + 16 * (kvb ^ (d & 7))),
                 VpT + (size_t)d * T_ + j0 + kvb * 4);
        }
        cp_commit();
        cp_wait0();
        __syncthreads();

        // ---- S = Q K^T ----
        float c[8][4];
#pragma unroll
        for (int nf = 0; nf < 8; nf++)
#pragma unroll
            for (int i = 0; i < 4; i++) c[nf][i] = 0.f;

        const uint32_t aBaseQ = QsB + (uint32_t)((warp * 16 + aRow) * LDQ + aColOff) * 4u;
#pragma unroll
        for (int kf = 0; kf < 8; kf++) {
            uint32_t a[4];
            ldsm4(a[0], a[1], a[2], a[3], aBaseQ + (uint32_t)(kf * 8) * 4u);
#pragma unroll
            for (int nfp = 0; nfp < 4; nfp++) {
                uint32_t b0, b1, b2, b3;
                ldsm4(b0, b1, b2, b3, bK[nfp] + (uint32_t)(kf * 32));
                mma_tf32(c[2 * nfp],     a, b0, b1);
                mma_tf32(c[2 * nfp + 1], a, b2, b3);
            }
        }

        // ---- causal mask (last two tiles only) ----
        if (jt >= 2 * qt) {
            int row0 = q0 + warp * 16 + gid;
#pragma unroll
            for (int nf = 0; nf < 8; nf++) {
                int col = j0 + nf * 8 + tig * 2;
                if (col     > row0)     c[nf][0] = -INFINITY;
                if (col + 1 > row0)     c[nf][1] = -INFINITY;
                if (col     > row0 + 8) c[nf][2] = -INFINITY;
                if (col + 1 > row0 + 8) c[nf][3] = -INFINITY;
            }
        }

        // ---- online softmax ----
        float rm0 = -INFINITY, rm1 = -INFINITY;
#pragma unroll
        for (int nf = 0; nf < 8; nf++) {
            rm0 = fmaxf(rm0, fmaxf(c[nf][0], c[nf][1]));
            rm1 = fmaxf(rm1, fmaxf(c[nf][2], c[nf][3]));
        }
#pragma unroll
        for (int off = 1; off < 4; off <<= 1) {
            rm0 = fmaxf(rm0, __shfl_xor_sync(0xffffffffu, rm0, off));
            rm1 = fmaxf(rm1, __shfl_xor_sync(0xffffffffu, rm1, off));
        }
        float mn0 = fmaxf(mr0, rm0);
        float mn1 = fmaxf(mr1, rm1);
        float al0 = exp2f((mr0 - mn0) * sc);
        float al1 = exp2f((mr1 - mn1) * sc);
        float rs0 = 0.f, rs1 = 0.f;
#pragma unroll
        for (int nf = 0; nf < 8; nf++) {
            c[nf][0] = exp2f((c[nf][0] - mn0) * sc);
            c[nf][1] = exp2f((c[nf][1] - mn0) * sc);
            c[nf][2] = exp2f((c[nf][2] - mn1) * sc);
            c[nf][3] = exp2f((c[nf][3] - mn1) * sc);
            rs0 += c[nf][0] + c[nf][1];
            rs1 += c[nf][2] + c[nf][3];
        }
#pragma unroll
        for (int off = 1; off < 4; off <<= 1) {
            rs0 += __shfl_xor_sync(0xffffffffu, rs0, off);
            rs1 += __shfl_xor_sync(0xffffffffu, rs1, off);
        }
        l0 = l0 * al0 + rs0;
        l1 = l1 * al1 + rs1;
        mr0 = mn0;
        mr1 = mn1;
#pragma unroll
        for (int nf = 0; nf < 8; nf++) {
            accO[nf][0] *= al0;
            accO[nf][1] *= al0;
            accO[nf][2] *= al1;
            accO[nf][3] *= al1;
        }

        // ---- stage P ----
        {
            uint32_t p0 = PsB + (uint32_t)((warp * 16 + gid) * LDP + tig * 2) * 4u;
            uint32_t p1 = p0 + (uint32_t)(8 * LDP) * 4u;
#pragma unroll
            for (int nf = 0; nf < 8; nf++) {
                sts64(p0 + (uint32_t)(nf * 32), f2tf32(c[nf][0]), f2tf32(c[nf][1]));
                sts64(p1 + (uint32_t)(nf * 32), f2tf32(c[nf][2]), f2tf32(c[nf][3]));
            }
        }
        __syncwarp();

        // ---- O += P @ V ----
        const uint32_t aBaseP = PsB + (uint32_t)((warp * 16 + aRow) * LDP + aColOff) * 4u;
#pragma unroll
        for (int kf = 0; kf < 8; kf++) {
            uint32_t a[4];
            ldsm4(a[0], a[1], a[2], a[3], aBaseP + (uint32_t)(kf * 8) * 4u);
#pragma unroll
            for (int nfp = 0; nfp < 4; nfp++) {
                uint32_t b0, b1, b2, b3;
                ldsm4(b0, b1, b2, b3, VtB + (bV[nfp] ^ (uint32_t)(kf << 5)));
                mma_tf32(accO[2 * nfp],     a, b0, b1);
                mma_tf32(accO[2 * nfp + 1], a, b2, b3);
            }
        }
        __syncwarp();
    }

    // ---- finalize; write tf32-rounded to g_y [B,T,H*P] ----
    float inv0 = 1.f / l0;
    float inv1 = 1.f / l1;
    int rowg = q0 + warp * 16 + gid;
    float* y0 = g_y + ((size_t)(b * T_ + rowg)) * D_ + h * 64 + tig * 2;
    float* y1 = y0 + 8 * (size_t)D_;
#pragma unroll
    for (int nf = 0; nf < 8; nf++) {
        *(float2*)&y0[nf * 8] = make_float2(f2tf32f(accO[nf][0] * inv0),
                                            f2tf32f(accO[nf][1] * inv0));
        *(float2*)&y1[nf * 8] = make_float2(f2tf32f(accO[nf][2] * inv1),
                                            f2tf32f(accO[nf][3] * inv1));
    }
}

// ---------------------------------------------------------------------------
extern "C" void kernel_launch(void* const* d_in, const int* in_sizes, int n_in,
                              void* d_out, int out_size)
{
    const float* x  = (const float*)d_in[0];
    const float* Wq = (const float*)d_in[2];
    const float* Wk = (const float*)d_in[3];
    const float* Wv = (const float*)d_in[4];
    const float* Wo = (const float*)d_in[5];
    float* out = (float*)d_out;

    cudaFuncSetAttribute(gemm_tc<0>, cudaFuncAttributeMaxDynamicSharedMemorySize,
                         GEMM_SMEM_BYTES);
    cudaFuncSetAttribute(gemm_tc<1>, cudaFuncAttributeMaxDynamicSharedMemorySize,
                         GEMM_SMEM_BYTES);
    cudaFuncSetAttribute(attn_tc, cudaFuncAttributeMaxDynamicSharedMemorySize,
                         ATTN_SMEM_BYTES);

    // Round x; round + transpose weights
    prep_x<<<8192, 256>>>(x);
    prep_wt<<<dim3(32, 32, 4), 256>>>(Wq, Wk, Wv, Wo);

    // QKV projections (V written transposed); block 128x256
    gemm_tc<0><<<dim3(4, 64, 3), 256, GEMM_SMEM_BYTES>>>(nullptr);

    // Flash attention (2 CTAs/SM)
    attn_tc<<<dim3(T_/128, B_*H_), 256, ATTN_SMEM_BYTES>>>();

    // Output projection
    gemm_tc<1><<<dim3(4, 64, 1), 256, GEMM_SMEM_BYTES>>>(out);
}

// round 8
// speedup vs baseline: 1.1253x; 1.0244x over previous
#include <cuda_runtime.h>
#include <math.h>
#include <stdint.h>

#define B_ 4
#define T_ 2048
#define D_ 1024
#define H_ 16
#define P_ 64
#define M_ (B_*T_)   // 8192

// Scratch (allocation-free rule: __device__ globals)
__device__ float g_q[(size_t)B_*H_*T_*P_];
__device__ float g_k[(size_t)B_*H_*T_*P_];
__device__ float g_v[(size_t)B_*H_*T_*P_];   // layout [B,H,P,T] (transposed V!)
__device__ float g_y[(size_t)M_*D_];
__device__ float g_xr[(size_t)M_*D_];        // x rounded to tf32
__device__ float g_wt[(size_t)4*1024*1024];  // W^T (n-major), tf32-rounded

// ---------------------------------------------------------------------------
// Helpers
// ---------------------------------------------------------------------------
__device__ __forceinline__ uint32_t f2tf32(float x) {
    uint32_t r;
    asm("cvt.rna.tf32.f32 %0, %1;" : "=r"(r) : "f"(x));
    return r;
}
__device__ __forceinline__ float f2tf32f(float x) {
    return __uint_as_float(f2tf32(x));
}
__device__ __forceinline__ uint32_t smem_u32(const void* p) {
    return (uint32_t)__cvta_generic_to_shared(p);
}
__device__ __forceinline__ void ldsm4(uint32_t& r0, uint32_t& r1,
                                      uint32_t& r2, uint32_t& r3, uint32_t addr) {
    asm volatile("ldmatrix.sync.aligned.m8n8.x4.shared.b16 {%0,%1,%2,%3}, [%4];"
                 : "=r"(r0), "=r"(r1), "=r"(r2), "=r"(r3) : "r"(addr));
}
__device__ __forceinline__ void mma_tf32(float c[4], const uint32_t a[4],
                                         uint32_t b0, uint32_t b1) {
    asm volatile(
        "mma.sync.aligned.m16n8k8.row.col.f32.tf32.tf32.f32 "
        "{%0,%1,%2,%3}, {%4,%5,%6,%7}, {%8,%9}, {%0,%1,%2,%3};"
        : "+f"(c[0]), "+f"(c[1]), "+f"(c[2]), "+f"(c[3])
        : "r"(a[0]), "r"(a[1]), "r"(a[2]), "r"(a[3]), "r"(b0), "r"(b1));
}
__device__ __forceinline__ void cp16(uint32_t dst, const void* src) {
    asm volatile("cp.async.cg.shared.global [%0], [%1], 16;"
                 :: "r"(dst), "l"(src));
}
__device__ __forceinline__ void cp_commit() {
    asm volatile("cp.async.commit_group;");
}
__device__ __forceinline__ void cp_wait0() {
    asm volatile("cp.async.wait_group 0;" ::: "memory");
}
__device__ __forceinline__ void cp_wait1() {
    asm volatile("cp.async.wait_group 1;" ::: "memory");
}
__device__ __forceinline__ void sts64(uint32_t dst, uint32_t a, uint32_t b) {
    asm volatile("st.shared.v2.b32 [%0], {%1,%2};" :: "r"(dst), "r"(a), "r"(b));
}

// ---------------------------------------------------------------------------
// Prep kernels: round x; round+transpose weights (Wt[n][k]).
// ---------------------------------------------------------------------------
__global__ void prep_x(const float* __restrict__ x)
{
    int i4 = blockIdx.x * blockDim.x + threadIdx.x;
    float4 v = ((const float4*)x)[i4];
    ((float4*)g_xr)[i4] = make_float4(f2tf32f(v.x), f2tf32f(v.y),
                                      f2tf32f(v.z), f2tf32f(v.w));
}

__global__ void prep_wt(const float* __restrict__ wq,
                        const float* __restrict__ wk,
                        const float* __restrict__ wv,
                        const float* __restrict__ wo)
{
    __shared__ float tile[32][33];
    const int z = blockIdx.z;
    const float* W = (z == 0) ? wq : (z == 1) ? wk : (z == 2) ? wv : wo;
    const int k0 = blockIdx.y * 32;
    const int n0 = blockIdx.x * 32;
    const int t = threadIdx.x;
    const int r = t >> 3;
    const int c4 = (t & 7) * 4;

    float4 v = *(const float4*)&W[(size_t)(k0 + r) * 1024 + n0 + c4];
    tile[r][c4 + 0] = f2tf32f(v.x);
    tile[r][c4 + 1] = f2tf32f(v.y);
    tile[r][c4 + 2] = f2tf32f(v.z);
    tile[r][c4 + 3] = f2tf32f(v.w);
    __syncthreads();
    float4 o = make_float4(tile[c4 + 0][r], tile[c4 + 1][r],
                           tile[c4 + 2][r], tile[c4 + 3][r]);
    *(float4*)&g_wt[(size_t)z * 1048576 + (size_t)(n0 + r) * 1024 + k0 + c4] = o;
}

// ---------------------------------------------------------------------------
// tf32 tensor-core GEMM (unchanged from R7): block 128x256, K-tile 32,
// 3-stage cp.async, 8 warps, warp 64x64.
// ---------------------------------------------------------------------------
#define GLD 36
#define AS_F (128*GLD)
#define BS_F (256*GLD)
#define STAGE_F (AS_F + BS_F)
#define GEMM_SMEM_BYTES (3*STAGE_F*4)

template <int MODE>
__global__ __launch_bounds__(256, 1)
void gemm_tc(float* __restrict__ outp)
{
    extern __shared__ float sm_g[];
    const int m0 = blockIdx.y * 128;
    const int n0 = blockIdx.x * 256;
    const int z  = (MODE == 0) ? blockIdx.z : 3;

    const float* Ap = (MODE == 0) ? g_xr : g_y;
    const float* Wt = g_wt + (size_t)z * 1048576;
    float* Cq = nullptr;
    if (MODE == 0) Cq = (z == 0) ? g_q : ((z == 1) ? g_k : g_v);

    const int tid  = threadIdx.x;
    const int lane = tid & 31;
    const int warp = tid >> 5;
    const int wm = (warp >> 2) * 64;
    const int wn = (warp & 3) * 64;
    const int gid = lane >> 2;
    const int tig = lane & 3;

    const int aRow    = (lane < 16) ? lane : (lane - 16);
    const int aColOff = (lane < 16) ? 0 : 4;
    const int rowRel  = ((lane >> 4) << 3) + (lane & 7);
    const int hb      = (lane >> 3) & 1;

    const uint32_t smBase = smem_u32(sm_g);
    const uint32_t aOff = (uint32_t)((wm + aRow) * GLD + aColOff) * 4u;
    uint32_t bOff[4];
#pragma unroll
    for (int nfp = 0; nfp < 4; nfp++)
        bOff[nfp] = (uint32_t)((wn + nfp * 16 + rowRel) * GLD + hb * 4) * 4u
                    + (uint32_t)AS_F * 4u;

    float acc[4][8][4];
#pragma unroll
    for (int mf = 0; mf < 4; mf++)
#pragma unroll
        for (int nf = 0; nf < 8; nf++)
#pragma unroll
            for (int i = 0; i < 4; i++) acc[mf][nf][i] = 0.f;

    auto cpStage = [&](int kt, int s) {
        uint32_t As = smBase + (uint32_t)(s * STAGE_F) * 4u;
        uint32_t Bs = As + (uint32_t)AS_F * 4u;
#pragma unroll
        for (int r = 0; r < 4; r++) {
            int lin  = tid + r * 256;
            int arow = lin >> 3;
            int ac4  = (lin & 7) * 4;
            cp16(As + (uint32_t)(arow * GLD + ac4) * 4u,
                 Ap + (size_t)(m0 + arow) * 1024 + kt * 32 + ac4);
        }
#pragma unroll
        for (int r = 0; r < 8; r++) {
            int lin  = tid + r * 256;
            int brow = lin >> 3;
            int bc4  = (lin & 7) * 4;
            cp16(Bs + (uint32_t)(brow * GLD + bc4) * 4u,
                 Wt + (size_t)(n0 + brow) * 1024 + kt * 32 + bc4);
        }
        cp_commit();
    };

    cpStage(0, 0);
    cpStage(1, 1);

    for (int kt = 0; kt < 32; kt++) {
        if (kt < 31) cp_wait1(); else cp_wait0();
        __syncthreads();
        if (kt + 2 < 32) cpStage(kt + 2, (kt + 2) % 3);

        const uint32_t stB = smBase + (uint32_t)((kt % 3) * STAGE_F) * 4u;
        const uint32_t aB  = stB + aOff;
#pragma unroll
        for (int kf = 0; kf < 4; kf++) {
            uint32_t a[4][4];
#pragma unroll
            for (int mf = 0; mf < 4; mf++)
                ldsm4(a[mf][0], a[mf][1], a[mf][2], a[mf][3],
                      aB + (uint32_t)(mf * 16 * GLD + kf * 8) * 4u);
            uint32_t b[8][2];
#pragma unroll
            for (int nfp = 0; nfp < 4; nfp++)
                ldsm4(b[2*nfp][0], b[2*nfp][1], b[2*nfp+1][0], b[2*nfp+1][1],
                      stB + bOff[nfp] + (uint32_t)(kf * 32));
#pragma unroll
            for (int mf = 0; mf < 4; mf++)
#pragma unroll
                for (int nf = 0; nf < 8; nf++)
                    mma_tf32(acc[mf][nf], a[mf], b[nf][0], b[nf][1]);
        }
    }

#pragma unroll
    for (int mf = 0; mf < 4; mf++) {
#pragma unroll
        for (int nf = 0; nf < 8; nf++) {
            int row = m0 + wm + mf * 16 + gid;
            int col = n0 + wn + nf * 8 + tig * 2;
#pragma unroll
            for (int half = 0; half < 2; half++) {
                int rr = row + half * 8;
                float v0 = acc[mf][nf][half * 2];
                float v1 = acc[mf][nf][half * 2 + 1];
                if (MODE == 0) {
                    int b = rr >> 11;
                    int t = rr & 2047;
                    int h = col >> 6;
                    int p = col & 63;
                    if (z == 2) {
                        size_t o = (((size_t)(b * H_ + h) * P_ + p) * T_ + t);
                        Cq[o]      = f2tf32f(v0);
                        Cq[o + T_] = f2tf32f(v1);
                    } else {
                        *(float2*)&Cq[(((size_t)(b * H_ + h) * T_ + t) * P_ + p)] =
                            make_float2(f2tf32f(v0), f2tf32f(v1));
                    }
                } else {
                    *(float2*)&outp[(size_t)rr * 1024 + col] = make_float2(v0, v1);
                }
            }
        }
    }
}

// ---------------------------------------------------------------------------
// tf32 tensor-core flash attention, causal.
// 256 thr = 8 warps; warp tile 32 q-rows (2 m-frags) -> block 256 q-rows.
// kv tiles of 64, DOUBLE-BUFFERED via cp.async. occ 1 (202KB smem).
// Per-warp causal tile skip: warp w computes nt_w = 4qt + (w>>1) + 1 tiles;
// mask applied only on its own diagonal tile (jt == nt_w-1).
// ---------------------------------------------------------------------------
#define LDQ 68
#define QS_F (256*LDQ)                 // 17408
#define KS_F (64*LDQ)                  // 4352
#define VT_F (64*64)                   // 4096
#define PS_F (256*LDQ)                 // 17408
#define OFF_KS0 QS_F
#define OFF_KS1 (QS_F + KS_F)
#define OFF_VT0 (QS_F + 2*KS_F)        // 26112 (x4 = 104448, 256B aligned)
#define OFF_VT1 (QS_F + 2*KS_F + VT_F) // 30208 (x4 = 120832, 256B aligned)
#define OFF_PS  (QS_F + 2*KS_F + 2*VT_F)
#define ATTN_SMEM_BYTES ((OFF_PS + PS_F)*4)   // 206848

__global__ __launch_bounds__(256, 1)
void attn_tc()
{
    extern __shared__ float sm[];

    const int bh = blockIdx.y;
    const int b  = bh >> 4;
    const int h  = bh & 15;
    const int qt = (int)gridDim.x - 1 - (int)blockIdx.x;  // heavy blocks first
    const int q0 = qt * 256;

    const size_t base = (size_t)bh * T_ * P_;
    const float* Qp  = g_q + base;
    const float* Kp  = g_k + base;
    const float* VpT = g_v + base;   // [d][t] per (b,h)

    const int tid  = threadIdx.x;
    const int lane = tid & 31;
    const int warp = tid >> 5;
    const int gid  = lane >> 2;
    const int tig  = lane & 3;
    const int aRow    = (lane < 16) ? lane : (lane - 16);
    const int aColOff = (lane < 16) ? 0 : 4;

    const uint32_t smBase = smem_u32(sm);
    const uint32_t QsB = smBase;
    const uint32_t KsB[2] = { smBase + OFF_KS0 * 4, smBase + OFF_KS1 * 4 };
    const uint32_t VtB[2] = { smBase + OFF_VT0 * 4, smBase + OFF_VT1 * 4 };
    const uint32_t PsB = smBase + OFF_PS * 4;

    const int rowRel = ((lane >> 4) << 3) + (lane & 7);
    const uint32_t hb = (lane >> 3) & 1;
    uint32_t bKrel[4], bVrel[4];
#pragma unroll
    for (int nfp = 0; nfp < 4; nfp++) {
        int row = nfp * 16 + rowRel;
        bKrel[nfp] = (uint32_t)(row * LDQ + (int)hb * 4) * 4u;
        bVrel[nfp] = (uint32_t)(row * 256 + 16 * (row & 7)) ^ (hb << 4);
    }

    // Load Q tile (256 x 64) via cp.async
#pragma unroll
    for (int r = 0; r < 16; r++) {
        int it = tid + r * 256;
        int rw = it >> 4;
        int c4 = (it & 15) * 4;
        cp16(QsB + (uint32_t)(rw * LDQ + c4) * 4u,
             Qp + (size_t)(q0 + rw) * 64 + c4);
    }
    cp_commit();

    const int ntiles = 4 * qt + 4;
    const int wm = warp * 32;                       // within-block row offset
    const int nt_w = 4 * qt + (warp >> 1) + 1;      // tiles this warp computes

    auto loadKV = [&](int jt, int buf) {
        const int j0 = jt * 64;
#pragma unroll
        for (int r = 0; r < 4; r++) {
            int it = tid + r * 256;
            int rw = it >> 4;
            int c4 = (it & 15) * 4;
            cp16(KsB[buf] + (uint32_t)(rw * LDQ + c4) * 4u,
                 Kp + (size_t)(j0 + rw) * 64 + c4);
        }
#pragma unroll
        for (int r = 0; r < 4; r++) {
            int u   = tid + r * 256;
            int d   = u >> 4;
            int kvb = u & 15;
            cp16(VtB[buf] + (uint32_t)(d * 256 + 16 * (kvb ^ (d & 7))),
                 VpT + (size_t)d * T_ + j0 + kvb * 4);
        }
        cp_commit();
    };

    loadKV(0, 0);
    loadKV(1, 1);

    float accO[2][8][4];
#pragma unroll
    for (int mf = 0; mf < 2; mf++)
#pragma unroll
        for (int nf = 0; nf < 8; nf++)
#pragma unroll
            for (int i = 0; i < 4; i++) accO[mf][nf][i] = 0.f;
    float mr[2][2] = {{-INFINITY, -INFINITY}, {-INFINITY, -INFINITY}};
    float ll[2][2] = {{0.f, 0.f}, {0.f, 0.f}};

    const float sc = 0.18033688011112042f;   // 0.125 * log2(e)

    for (int jt = 0; jt < ntiles; jt++) {
        if (jt + 2 < ntiles) cp_wait1(); else cp_wait0();
        __syncthreads();

        if (jt < nt_w) {
            const int buf = jt & 1;
            const int j0  = jt * 64;

            // ---- S = Q K^T  (warp: 32 rows x 64 cols) ----
            float c[2][8][4];
#pragma unroll
            for (int mf = 0; mf < 2; mf++)
#pragma unroll
                for (int nf = 0; nf < 8; nf++)
#pragma unroll
                    for (int i = 0; i < 4; i++) c[mf][nf][i] = 0.f;

#pragma unroll
            for (int kf = 0; kf < 8; kf++) {
                uint32_t a[2][4];
#pragma unroll
                for (int mf = 0; mf < 2; mf++)
                    ldsm4(a[mf][0], a[mf][1], a[mf][2], a[mf][3],
                          QsB + (uint32_t)((wm + mf * 16 + aRow) * LDQ
                                           + aColOff + kf * 8) * 4u);
#pragma unroll
                for (int nfp = 0; nfp < 4; nfp++) {
                    uint32_t b0, b1, b2, b3;
                    ldsm4(b0, b1, b2, b3,
                          KsB[buf] + bKrel[nfp] + (uint32_t)(kf * 32));
#pragma unroll
                    for (int mf = 0; mf < 2; mf++) {
                        mma_tf32(c[mf][2 * nfp],     a[mf], b0, b1);
                        mma_tf32(c[mf][2 * nfp + 1], a[mf], b2, b3);
                    }
                }
            }

            // ---- causal mask (this warp's diagonal tile only) ----
            if (jt == nt_w - 1) {
#pragma unroll
                for (int mf = 0; mf < 2; mf++) {
                    int row0 = q0 + wm + mf * 16 + gid;
#pragma unroll
                    for (int nf = 0; nf < 8; nf++) {
                        int col = j0 + nf * 8 + tig * 2;
                        if (col     > row0)     c[mf][nf][0] = -INFINITY;
                        if (col + 1 > row0)     c[mf][nf][1] = -INFINITY;
                        if (col     > row0 + 8) c[mf][nf][2] = -INFINITY;
                        if (col + 1 > row0 + 8) c[mf][nf][3] = -INFINITY;
                    }
                }
            }

            // ---- online softmax (per mf, per 8-row half) ----
#pragma unroll
            for (int mf = 0; mf < 2; mf++) {
                float rm0 = -INFINITY, rm1 = -INFINITY;
#pragma unroll
                for (int nf = 0; nf < 8; nf++) {
                    rm0 = fmaxf(rm0, fmaxf(c[mf][nf][0], c[mf][nf][1]));
                    rm1 = fmaxf(rm1, fmaxf(c[mf][nf][2], c[mf][nf][3]));
                }
#pragma unroll
                for (int off = 1; off < 4; off <<= 1) {
                    rm0 = fmaxf(rm0, __shfl_xor_sync(0xffffffffu, rm0, off));
                    rm1 = fmaxf(rm1, __shfl_xor_sync(0xffffffffu, rm1, off));
                }
                float mn0 = fmaxf(mr[mf][0], rm0);
                float mn1 = fmaxf(mr[mf][1], rm1);
                float al0 = exp2f((mr[mf][0] - mn0) * sc);
                float al1 = exp2f((mr[mf][1] - mn1) * sc);
                float rs0 = 0.f, rs1 = 0.f;
#pragma unroll
                for (int nf = 0; nf < 8; nf++) {
                    c[mf][nf][0] = exp2f((c[mf][nf][0] - mn0) * sc);
                    c[mf][nf][1] = exp2f((c[mf][nf][1] - mn0) * sc);
                    c[mf][nf][2] = exp2f((c[mf][nf][2] - mn1) * sc);
                    c[mf][nf][3] = exp2f((c[mf][nf][3] - mn1) * sc);
                    rs0 += c[mf][nf][0] + c[mf][nf][1];
                    rs1 += c[mf][nf][2] + c[mf][nf][3];
                }
#pragma unroll
                for (int off = 1; off < 4; off <<= 1) {
                    rs0 += __shfl_xor_sync(0xffffffffu, rs0, off);
                    rs1 += __shfl_xor_sync(0xffffffffu, rs1, off);
                }
                ll[mf][0] = ll[mf][0] * al0 + rs0;
                ll[mf][1] = ll[mf][1] * al1 + rs1;
                mr[mf][0] = mn0;
                mr[mf][1] = mn1;
#pragma unroll
                for (int nf = 0; nf < 8; nf++) {
                    accO[mf][nf][0] *= al0;
                    accO[mf][nf][1] *= al0;
                    accO[mf][nf][2] *= al1;
                    accO[mf][nf][3] *= al1;
                }
            }

            // ---- stage P (warp-local rows) ----
#pragma unroll
            for (int mf = 0; mf < 2; mf++) {
                uint32_t p0 = PsB + (uint32_t)((wm + mf * 16 + gid) * LDQ
                                               + tig * 2) * 4u;
                uint32_t p1 = p0 + (uint32_t)(8 * LDQ) * 4u;
#pragma unroll
                for (int nf = 0; nf < 8; nf++) {
                    sts64(p0 + (uint32_t)(nf * 32),
                          f2tf32(c[mf][nf][0]), f2tf32(c[mf][nf][1]));
                    sts64(p1 + (uint32_t)(nf * 32),
                          f2tf32(c[mf][nf][2]), f2tf32(c[mf][nf][3]));
                }
            }
            __syncwarp();

            // ---- O += P @ V ----
#pragma unroll
            for (int kf = 0; kf < 8; kf++) {
                uint32_t a[2][4];
#pragma unroll
                for (int mf = 0; mf < 2; mf++)
                    ldsm4(a[mf][0], a[mf][1], a[mf][2], a[mf][3],
                          PsB + (uint32_t)((wm + mf * 16 + aRow) * LDQ
                                           + aColOff + kf * 8) * 4u);
#pragma unroll
                for (int nfp = 0; nfp < 4; nfp++) {
                    uint32_t b0, b1, b2, b3;
                    ldsm4(b0, b1, b2, b3,
                          VtB[buf] + (bVrel[nfp] ^ (uint32_t)(kf << 5)));
#pragma unroll
                    for (int mf = 0; mf < 2; mf++) {
                        mma_tf32(accO[mf][2 * nfp],     a[mf], b0, b1);
                        mma_tf32(accO[mf][2 * nfp + 1], a[mf], b2, b3);
                    }
                }
            }
            __syncwarp();
        }

        __syncthreads();
        if (jt + 2 < ntiles) loadKV(jt + 2, jt & 1);
    }

    // ---- finalize; write tf32-rounded to g_y [B,T,H*P] ----
#pragma unroll
    for (int mf = 0; mf < 2; mf++) {
        float inv0 = 1.f / ll[mf][0];
        float inv1 = 1.f / ll[mf][1];
        int rowg = q0 + wm + mf * 16 + gid;
        float* y0 = g_y + ((size_t)(b * T_ + rowg)) * D_ + h * 64 + tig * 2;
        float* y1 = y0 + 8 * (size_t)D_;
#pragma unroll
        for (int nf = 0; nf < 8; nf++) {
            *(float2*)&y0[nf * 8] = make_float2(f2tf32f(accO[mf][nf][0] * inv0),
                                                f2tf32f(accO[mf][nf][1] * inv0));
            *(float2*)&y1[nf * 8] = make_float2(f2tf32f(accO[mf][nf][2] * inv1),
                                                f2tf32f(accO[mf][nf][3] * inv1));
        }
    }
}

// ---------------------------------------------------------------------------
extern "C" void kernel_launch(void* const* d_in, const int* in_sizes, int n_in,
                              void* d_out, int out_size)
{
    const float* x  = (const float*)d_in[0];
    const float* Wq = (const float*)d_in[2];
    const float* Wk = (const float*)d_in[3];
    const float* Wv = (const float*)d_in[4];
    const float* Wo = (const float*)d_in[5];
    float* out = (float*)d_out;

    cudaFuncSetAttribute(gemm_tc<0>, cudaFuncAttributeMaxDynamicSharedMemorySize,
                         GEMM_SMEM_BYTES);
    cudaFuncSetAttribute(gemm_tc<1>, cudaFuncAttributeMaxDynamicSharedMemorySize,
                         GEMM_SMEM_BYTES);
    cudaFuncSetAttribute(attn_tc, cudaFuncAttributeMaxDynamicSharedMemorySize,
                         ATTN_SMEM_BYTES);

    // Round x; round + transpose weights
    prep_x<<<8192, 256>>>(x);
    prep_wt<<<dim3(32, 32, 4), 256>>>(Wq, Wk, Wv, Wo);

    // QKV projections (V written transposed)
    gemm_tc<0><<<dim3(4, 64, 3), 256, GEMM_SMEM_BYTES>>>(nullptr);

    // Flash attention (256-row q blocks, double-buffered K/V)
    attn_tc<<<dim3(T_/256, B_*H_), 256, ATTN_SMEM_BYTES>>>();

    // Output projection
    gemm_tc<1><<<dim3(4, 64, 1), 256, GEMM_SMEM_BYTES>>>(out);
}

// round 9
// speedup vs baseline: 1.8870x; 1.6769x over previous
#include <cuda_runtime.h>
#include <cuda_fp16.h>
#include <math.h>
#include <stdint.h>

#define B_ 4
#define T_ 2048
#define D_ 1024
#define H_ 16
#define P_ 64
#define M_ (B_*T_)   // 8192

// Scratch (allocation-free rule: __device__ globals), fp16
__device__ __align__(16) __half g_qh[(size_t)B_*H_*T_*P_];
__device__ __align__(16) __half g_kh[(size_t)B_*H_*T_*P_];
__device__ __align__(16) __half g_vh[(size_t)B_*H_*T_*P_];   // [B,H,P,T] transposed
__device__ __align__(16) __half g_yh[(size_t)M_*D_];
__device__ __align__(16) __half g_xh[(size_t)M_*D_];         // x in fp16
__device__ __align__(16) __half g_wth[(size_t)4*1024*1024];  // W^T (n-major) fp16

// ---------------------------------------------------------------------------
// Helpers
// ---------------------------------------------------------------------------
__device__ __forceinline__ uint32_t pack_h2(float lo, float hi) {
    uint32_t r;
    asm("cvt.rn.f16x2.f32 %0, %1, %2;" : "=r"(r) : "f"(hi), "f"(lo));
    return r;
}
__device__ __forceinline__ uint32_t smem_u32(const void* p) {
    return (uint32_t)__cvta_generic_to_shared(p);
}
__device__ __forceinline__ void ldsm4(uint32_t& r0, uint32_t& r1,
                                      uint32_t& r2, uint32_t& r3, uint32_t addr) {
    asm volatile("ldmatrix.sync.aligned.m8n8.x4.shared.b16 {%0,%1,%2,%3}, [%4];"
                 : "=r"(r0), "=r"(r1), "=r"(r2), "=r"(r3) : "r"(addr));
}
__device__ __forceinline__ void mma_f16(float c[4], const uint32_t a[4],
                                        uint32_t b0, uint32_t b1) {
    asm volatile(
        "mma.sync.aligned.m16n8k16.row.col.f32.f16.f16.f32 "
        "{%0,%1,%2,%3}, {%4,%5,%6,%7}, {%8,%9}, {%0,%1,%2,%3};"
        : "+f"(c[0]), "+f"(c[1]), "+f"(c[2]), "+f"(c[3])
        : "r"(a[0]), "r"(a[1]), "r"(a[2]), "r"(a[3]), "r"(b0), "r"(b1));
}
__device__ __forceinline__ void cp16(uint32_t dst, const void* src) {
    asm volatile("cp.async.cg.shared.global [%0], [%1], 16;"
                 :: "r"(dst), "l"(src));
}
__device__ __forceinline__ void cp_commit() {
    asm volatile("cp.async.commit_group;");
}
__device__ __forceinline__ void cp_wait0() {
    asm volatile("cp.async.wait_group 0;" ::: "memory");
}
__device__ __forceinline__ void cp_wait1() {
    asm volatile("cp.async.wait_group 1;" ::: "memory");
}

// ---------------------------------------------------------------------------
// Prep: x -> fp16 ; W -> W^T fp16
// ---------------------------------------------------------------------------
__global__ void prep_x(const float* __restrict__ x)
{
    size_t i8 = blockIdx.x * 256 + threadIdx.x;   // 8 elems each
    const float4* xp = (const float4*)x;
    float4 v0 = xp[i8 * 2], v1 = xp[i8 * 2 + 1];
    uint4 o;
    o.x = pack_h2(v0.x, v0.y);
    o.y = pack_h2(v0.z, v0.w);
    o.z = pack_h2(v1.x, v1.y);
    o.w = pack_h2(v1.z, v1.w);
    ((uint4*)g_xh)[i8] = o;
}

__global__ void prep_wt(const float* __restrict__ wq,
                        const float* __restrict__ wk,
                        const float* __restrict__ wv,
                        const float* __restrict__ wo)
{
    __shared__ float tile[32][33];
    const int z = blockIdx.z;
    const float* W = (z == 0) ? wq : (z == 1) ? wk : (z == 2) ? wv : wo;
    const int k0 = blockIdx.y * 32;
    const int n0 = blockIdx.x * 32;
    const int t = threadIdx.x;
    const int r = t >> 3;
    const int c4 = (t & 7) * 4;

    float4 v = *(const float4*)&W[(size_t)(k0 + r) * 1024 + n0 + c4];
    tile[r][c4 + 0] = v.x;
    tile[r][c4 + 1] = v.y;
    tile[r][c4 + 2] = v.z;
    tile[r][c4 + 3] = v.w;
    __syncthreads();
    uint2 o;
    o.x = pack_h2(tile[c4 + 0][r], tile[c4 + 1][r]);
    o.y = pack_h2(tile[c4 + 2][r], tile[c4 + 3][r]);
    *(uint2*)&g_wth[(size_t)z * 1048576 + (size_t)(n0 + r) * 1024 + k0 + c4] = o;
}

// ---------------------------------------------------------------------------
// fp16 tensor-core GEMM: C[M,1024] = A * W.  Block 128(M)x256(N), K-tile 32,
// 3-stage cp.async. 256 thr = 8 warps (2M x 4N), warp 64x64.
// Rows padded to 40 halfs (80B = 5*16B -> ldmatrix conflict-free).
// MODE 0: A=g_xh, z->(Wq,Wk,Wv), out q/k [B,H,T,P] fp16; v [B,H,P,T] fp16.
// MODE 1: A=g_yh, W=Wo, C=d_out f32.
// ---------------------------------------------------------------------------
#define GLDH 40
#define AS_H (128*GLDH)            // 5120 halfs
#define BS_H (256*GLDH)            // 10240 halfs
#define STAGE_H (AS_H + BS_H)      // 15360 halfs = 30720 B
#define GEMM_SMEM_BYTES (3*STAGE_H*2)   // 92160

template <int MODE>
__global__ __launch_bounds__(256, 1)
void gemm_tc(float* __restrict__ outp)
{
    extern __shared__ __half sm_g[];
    const int m0 = blockIdx.y * 128;
    const int n0 = blockIdx.x * 256;
    const int z  = (MODE == 0) ? blockIdx.z : 3;

    const __half* Ap = (MODE == 0) ? g_xh : g_yh;
    const __half* Wt = g_wth + (size_t)z * 1048576;
    __half* Cq = nullptr;
    if (MODE == 0) Cq = (z == 0) ? g_qh : ((z == 1) ? g_kh : g_vh);

    const int tid  = threadIdx.x;
    const int lane = tid & 31;
    const int warp = tid >> 5;
    const int wm = (warp >> 2) * 64;
    const int wn = (warp & 3) * 64;
    const int gid = lane >> 2;
    const int tig = lane & 3;

    const int aRow = lane & 15;
    const uint32_t aHi = (uint32_t)(lane >> 4) * 16u;
    const int bRowRel = (lane & 7) + ((lane >> 4) << 3);
    const uint32_t bHi = (uint32_t)((lane >> 3) & 1) * 16u;

    const uint32_t smBase = smem_u32(sm_g);
    uint32_t aOff[4], bOff[4];
#pragma unroll
    for (int mf = 0; mf < 4; mf++)
        aOff[mf] = (uint32_t)((wm + mf * 16 + aRow) * GLDH) * 2u + aHi;
#pragma unroll
    for (int nfp = 0; nfp < 4; nfp++)
        bOff[nfp] = (uint32_t)((wn + nfp * 16 + bRowRel) * GLDH) * 2u + bHi
                    + (uint32_t)AS_H * 2u;

    float acc[4][8][4];
#pragma unroll
    for (int mf = 0; mf < 4; mf++)
#pragma unroll
        for (int nf = 0; nf < 8; nf++)
#pragma unroll
            for (int i = 0; i < 4; i++) acc[mf][nf][i] = 0.f;

    auto cpStage = [&](int kt, int s) {
        uint32_t As = smBase + (uint32_t)(s * STAGE_H) * 2u;
        uint32_t Bs = As + (uint32_t)AS_H * 2u;
#pragma unroll
        for (int r = 0; r < 2; r++) {         // A: 128 rows x 4 chunks
            int lin = tid + r * 256;
            int row = lin >> 2;
            int ck  = lin & 3;
            cp16(As + (uint32_t)(row * GLDH + ck * 8) * 2u,
                 Ap + (size_t)(m0 + row) * 1024 + kt * 32 + ck * 8);
        }
#pragma unroll
        for (int r = 0; r < 4; r++) {         // B: 256 rows x 4 chunks
            int lin = tid + r * 256;
            int row = lin >> 2;
            int ck  = lin & 3;
            cp16(Bs + (uint32_t)(row * GLDH + ck * 8) * 2u,
                 Wt + (size_t)(n0 + row) * 1024 + kt * 32 + ck * 8);
        }
        cp_commit();
    };

    cpStage(0, 0);
    cpStage(1, 1);

    for (int kt = 0; kt < 32; kt++) {
        if (kt < 31) cp_wait1(); else cp_wait0();
        __syncthreads();
        if (kt + 2 < 32) cpStage(kt + 2, (kt + 2) % 3);

        const uint32_t stB = smBase + (uint32_t)((kt % 3) * STAGE_H) * 2u;
#pragma unroll
        for (int kf = 0; kf < 2; kf++) {
            uint32_t a[4][4];
#pragma unroll
            for (int mf = 0; mf < 4; mf++)
                ldsm4(a[mf][0], a[mf][1], a[mf][2], a[mf][3],
                      stB + aOff[mf] + (uint32_t)(kf * 32));
            uint32_t b[8][2];
#pragma unroll
            for (int nfp = 0; nfp < 4; nfp++)
                ldsm4(b[2*nfp][0], b[2*nfp][1], b[2*nfp+1][0], b[2*nfp+1][1],
                      stB + bOff[nfp] + (uint32_t)(kf * 32));
#pragma unroll
            for (int mf = 0; mf < 4; mf++)
#pragma unroll
                for (int nf = 0; nf < 8; nf++)
                    mma_f16(acc[mf][nf], a[mf], b[nf][0], b[nf][1]);
        }
    }

    // Epilogue
#pragma unroll
    for (int mf = 0; mf < 4; mf++) {
#pragma unroll
        for (int nf = 0; nf < 8; nf++) {
            int row = m0 + wm + mf * 16 + gid;
            int col = n0 + wn + nf * 8 + tig * 2;
#pragma unroll
            for (int half = 0; half < 2; half++) {
                int rr = row + half * 8;
                float v0 = acc[mf][nf][half * 2];
                float v1 = acc[mf][nf][half * 2 + 1];
                if (MODE == 0) {
                    int b = rr >> 11;
                    int t = rr & 2047;
                    int h = col >> 6;
                    int p = col & 63;
                    if (z == 2) {
                        size_t o = (((size_t)(b * H_ + h) * P_ + p) * T_ + t);
                        Cq[o]      = __float2half_rn(v0);
                        Cq[o + T_] = __float2half_rn(v1);
                    } else {
                        *(uint32_t*)&Cq[(((size_t)(b * H_ + h) * T_ + t) * P_ + p)] =
                            pack_h2(v0, v1);
                    }
                } else {
                    *(float2*)&outp[(size_t)rr * 1024 + col] = make_float2(v0, v1);
                }
            }
        }
    }
}

// ---------------------------------------------------------------------------
// fp16 tensor-core flash attention, causal.
// 128 thr = 4 warps x 32 q-rows = 128-row blocks; kv tiles 64, double-buffered.
// occ 2. P kept in registers (FA2 fragment-layout trick, no smem round trip).
// Rows padded to 72 halfs (144B = 9*16B -> ldmatrix conflict-free).
// ---------------------------------------------------------------------------
#define LDH 72
#define QS_H (128*LDH)                 // 9216 halfs
#define KS_H (64*LDH)                  // 4608
#define OFF_K0 QS_H
#define OFF_K1 (QS_H + KS_H)
#define OFF_V0 (QS_H + 2*KS_H)
#define OFF_V1 (QS_H + 3*KS_H)
#define ATTN_SMEM_BYTES ((QS_H + 4*KS_H)*2)    // 55296; x2 CTAs = 110592

__global__ __launch_bounds__(128, 2)
void attn_tc()
{
    extern __shared__ __half sm[];

    const int bh = blockIdx.y;
    const int b  = bh >> 4;
    const int h  = bh & 15;
    const int qt = (int)gridDim.x - 1 - (int)blockIdx.x;  // heavy blocks first
    const int q0 = qt * 128;

    const size_t base = (size_t)bh * T_ * P_;
    const __half* Qp  = g_qh + base;
    const __half* Kp  = g_kh + base;
    const __half* VpT = g_vh + base;   // [d][t]

    const int tid  = threadIdx.x;
    const int lane = tid & 31;
    const int warp = tid >> 5;
    const int gid  = lane >> 2;
    const int tig  = lane & 3;
    const int aRow = lane & 15;
    const uint32_t aHi = (uint32_t)(lane >> 4) * 16u;
    const int bRowRel = (lane & 7) + ((lane >> 4) << 3);
    const uint32_t bHi = (uint32_t)((lane >> 3) & 1) * 16u;

    const uint32_t smBase = smem_u32(sm);
    const uint32_t QsB = smBase;
    const uint32_t KsB[2] = { smBase + OFF_K0 * 2, smBase + OFF_K1 * 2 };
    const uint32_t VtB[2] = { smBase + OFF_V0 * 2, smBase + OFF_V1 * 2 };

    const int wm = warp * 32;
    uint32_t qOff[2], bOffR[4];
#pragma unroll
    for (int mf = 0; mf < 2; mf++)
        qOff[mf] = (uint32_t)((wm + mf * 16 + aRow) * LDH) * 2u + aHi;
#pragma unroll
    for (int nfp = 0; nfp < 4; nfp++)
        bOffR[nfp] = (uint32_t)((nfp * 16 + bRowRel) * LDH) * 2u + bHi;

    // Load Q tile (128 x 64)
#pragma unroll
    for (int r = 0; r < 8; r++) {
        int it = tid + r * 128;
        int rw = it >> 3;
        int ck = it & 7;
        cp16(QsB + (uint32_t)(rw * LDH + ck * 8) * 2u,
             Qp + (size_t)(q0 + rw) * 64 + ck * 8);
    }
    cp_commit();

    const int ntiles = 2 * qt + 2;
    const int nt_w = 2 * qt + 1 + (warp >> 1);

    auto loadKV = [&](int jt, int buf) {
        const int j0 = jt * 64;
#pragma unroll
        for (int r = 0; r < 4; r++) {
            int it = tid + r * 128;
            int rw = it >> 3;
            int ck = it & 7;
            cp16(KsB[buf] + (uint32_t)(rw * LDH + ck * 8) * 2u,
                 Kp + (size_t)(j0 + rw) * 64 + ck * 8);
        }
#pragma unroll
        for (int r = 0; r < 4; r++) {
            int it = tid + r * 128;
            int d  = it >> 3;
            int tc = it & 7;
            cp16(VtB[buf] + (uint32_t)(d * LDH + tc * 8) * 2u,
                 VpT + (size_t)d * T_ + j0 + tc * 8);
        }
        cp_commit();
    };

    loadKV(0, 0);
    loadKV(1, 1);

    float accO[2][8][4];
#pragma unroll
    for (int mf = 0; mf < 2; mf++)
#pragma unroll
        for (int nf = 0; nf < 8; nf++)
#pragma unroll
            for (int i = 0; i < 4; i++) accO[mf][nf][i] = 0.f;
    float mr[2][2] = {{-INFINITY, -INFINITY}, {-INFINITY, -INFINITY}};
    float ll[2][2] = {{0.f, 0.f}, {0.f, 0.f}};

    const float sc = 0.18033688011112042f;   // 0.125 * log2(e)

    for (int jt = 0; jt < ntiles; jt++) {
        if (jt + 2 < ntiles) cp_wait1(); else cp_wait0();
        __syncthreads();

        if (jt < nt_w) {
            const int buf = jt & 1;
            const int j0  = jt * 64;

            // ---- S = Q K^T (warp: 32 rows x 64 cols) ----
            float c[2][8][4];
#pragma unroll
            for (int mf = 0; mf < 2; mf++)
#pragma unroll
                for (int nf = 0; nf < 8; nf++)
#pragma unroll
                    for (int i = 0; i < 4; i++) c[mf][nf][i] = 0.f;

#pragma unroll
            for (int kf = 0; kf < 4; kf++) {
                uint32_t a[2][4];
#pragma unroll
                for (int mf = 0; mf < 2; mf++)
                    ldsm4(a[mf][0], a[mf][1], a[mf][2], a[mf][3],
                          QsB + qOff[mf] + (uint32_t)(kf * 32));
#pragma unroll
                for (int nfp = 0; nfp < 4; nfp++) {
                    uint32_t b0, b1, b2, b3;
                    ldsm4(b0, b1, b2, b3,
                          KsB[buf] + bOffR[nfp] + (uint32_t)(kf * 32));
#pragma unroll
                    for (int mf = 0; mf < 2; mf++) {
                        mma_f16(c[mf][2 * nfp],     a[mf], b0, b1);
                        mma_f16(c[mf][2 * nfp + 1], a[mf], b2, b3);
                    }
                }
            }

            // ---- causal mask (this warp's diagonal tile only) ----
            if (jt == nt_w - 1) {
#pragma unroll
                for (int mf = 0; mf < 2; mf++) {
                    int row0 = q0 + wm + mf * 16 + gid;
#pragma unroll
                    for (int nf = 0; nf < 8; nf++) {
                        int col = j0 + nf * 8 + tig * 2;
                        if (col     > row0)     c[mf][nf][0] = -INFINITY;
                        if (col + 1 > row0)     c[mf][nf][1] = -INFINITY;
                        if (col     > row0 + 8) c[mf][nf][2] = -INFINITY;
                        if (col + 1 > row0 + 8) c[mf][nf][3] = -INFINITY;
                    }
                }
            }

            // ---- online softmax ----
#pragma unroll
            for (int mf = 0; mf < 2; mf++) {
                float rm0 = -INFINITY, rm1 = -INFINITY;
#pragma unroll
                for (int nf = 0; nf < 8; nf++) {
                    rm0 = fmaxf(rm0, fmaxf(c[mf][nf][0], c[mf][nf][1]));
                    rm1 = fmaxf(rm1, fmaxf(c[mf][nf][2], c[mf][nf][3]));
                }
#pragma unroll
                for (int off = 1; off < 4; off <<= 1) {
                    rm0 = fmaxf(rm0, __shfl_xor_sync(0xffffffffu, rm0, off));
                    rm1 = fmaxf(rm1, __shfl_xor_sync(0xffffffffu, rm1, off));
                }
                float mn0 = fmaxf(mr[mf][0], rm0);
                float mn1 = fmaxf(mr[mf][1], rm1);
                float al0 = exp2f((mr[mf][0] - mn0) * sc);
                float al1 = exp2f((mr[mf][1] - mn1) * sc);
                float rs0 = 0.f, rs1 = 0.f;
#pragma unroll
                for (int nf = 0; nf < 8; nf++) {
                    c[mf][nf][0] = exp2f((c[mf][nf][0] - mn0) * sc);
                    c[mf][nf][1] = exp2f((c[mf][nf][1] - mn0) * sc);
                    c[mf][nf][2] = exp2f((c[mf][nf][2] - mn1) * sc);
                    c[mf][nf][3] = exp2f((c[mf][nf][3] - mn1) * sc);
                    rs0 += c[mf][nf][0] + c[mf][nf][1];
                    rs1 += c[mf][nf][2] + c[mf][nf][3];
                }
#pragma unroll
                for (int off = 1; off < 4; off <<= 1) {
                    rs0 += __shfl_xor_sync(0xffffffffu, rs0, off);
                    rs1 += __shfl_xor_sync(0xffffffffu, rs1, off);
                }
                ll[mf][0] = ll[mf][0] * al0 + rs0;
                ll[mf][1] = ll[mf][1] * al1 + rs1;
                mr[mf][0] = mn0;
                mr[mf][1] = mn1;
#pragma unroll
                for (int nf = 0; nf < 8; nf++) {
                    accO[mf][nf][0] *= al0;
                    accO[mf][nf][1] *= al0;
                    accO[mf][nf][2] *= al1;
                    accO[mf][nf][3] *= al1;
                }
            }

            // ---- O += P @ V : P packed straight from S fragments ----
#pragma unroll
            for (int kf = 0; kf < 4; kf++) {
                uint32_t pa[2][4];
#pragma unroll
                for (int mf = 0; mf < 2; mf++) {
                    pa[mf][0] = pack_h2(c[mf][2*kf][0],   c[mf][2*kf][1]);
                    pa[mf][1] = pack_h2(c[mf][2*kf][2],   c[mf][2*kf][3]);
                    pa[mf][2] = pack_h2(c[mf][2*kf+1][0], c[mf][2*kf+1][1]);
                    pa[mf][3] = pack_h2(c[mf][2*kf+1][2], c[mf][2*kf+1][3]);
                }
#pragma unroll
                for (int nfp = 0; nfp < 4; nfp++) {
                    uint32_t b0, b1, b2, b3;
                    ldsm4(b0, b1, b2, b3,
                          VtB[buf] + bOffR[nfp] + (uint32_t)(kf * 32));
#pragma unroll
                    for (int mf = 0; mf < 2; mf++) {
                        mma_f16(accO[mf][2 * nfp],     pa[mf], b0, b1);
                        mma_f16(accO[mf][2 * nfp + 1], pa[mf], b2, b3);
                    }
                }
            }
        }

        __syncthreads();
        if (jt + 2 < ntiles) loadKV(jt + 2, jt & 1);
    }

    // ---- finalize; write fp16 y [B,T,H*P] ----
#pragma unroll
    for (int mf = 0; mf < 2; mf++) {
        float inv0 = 1.f / ll[mf][0];
        float inv1 = 1.f / ll[mf][1];
        int rowg = q0 + wm + mf * 16 + gid;
        __half* y0 = g_yh + ((size_t)(b * T_ + rowg)) * D_ + h * 64 + tig * 2;
        __half* y1 = y0 + 8 * (size_t)D_;
#pragma unroll
        for (int nf = 0; nf < 8; nf++) {
            *(uint32_t*)&y0[nf * 8] = pack_h2(accO[mf][nf][0] * inv0,
                                              accO[mf][nf][1] * inv0);
            *(uint32_t*)&y1[nf * 8] = pack_h2(accO[mf][nf][2] * inv1,
                                              accO[mf][nf][3] * inv1);
        }
    }
}

// ---------------------------------------------------------------------------
extern "C" void kernel_launch(void* const* d_in, const int* in_sizes, int n_in,
                              void* d_out, int out_size)
{
    const float* x  = (const float*)d_in[0];
    const float* Wq = (const float*)d_in[2];
    const float* Wk = (const float*)d_in[3];
    const float* Wv = (const float*)d_in[4];
    const float* Wo = (const float*)d_in[5];
    float* out = (float*)d_out;

    cudaFuncSetAttribute(gemm_tc<0>, cudaFuncAttributeMaxDynamicSharedMemorySize,
                         GEMM_SMEM_BYTES);
    cudaFuncSetAttribute(gemm_tc<1>, cudaFuncAttributeMaxDynamicSharedMemorySize,
                         GEMM_SMEM_BYTES);
    cudaFuncSetAttribute(attn_tc, cudaFuncAttributeMaxDynamicSharedMemorySize,
                         ATTN_SMEM_BYTES);

    // fp16 conversions
    prep_x<<<4096, 256>>>(x);
    prep_wt<<<dim3(32, 32, 4), 256>>>(Wq, Wk, Wv, Wo);

    // QKV projections (V written transposed)
    gemm_tc<0><<<dim3(4, 64, 3), 256, GEMM_SMEM_BYTES>>>(nullptr);

    // Flash attention (128-row q blocks, occ 2, register-resident P)
    attn_tc<<<dim3(T_/128, B_*H_), 128, ATTN_SMEM_BYTES>>>();

    // Output projection
    gemm_tc<1><<<dim3(4, 64, 1), 256, GEMM_SMEM_BYTES>>>(out);
}

// round 11
// speedup vs baseline: 2.3510x; 1.2459x over previous
#include <cuda_runtime.h>
#include <cuda_fp16.h>
#include <math.h>
#include <stdint.h>

#define B_ 4
#define T_ 2048
#define D_ 1024
#define H_ 16
#define P_ 64
#define M_ (B_*T_)   // 8192

// Scratch (allocation-free rule: __device__ globals), fp16
__device__ __align__(16) __half g_qh[(size_t)B_*H_*T_*P_];   // pre-scaled by 0.125*log2e
__device__ __align__(16) __half g_kh[(size_t)B_*H_*T_*P_];
__device__ __align__(16) __half g_vh[(size_t)B_*H_*T_*P_];   // [B,H,P,T] transposed
__device__ __align__(16) __half g_yh[(size_t)M_*D_];
__device__ __align__(16) __half g_xh[(size_t)M_*D_];
__device__ __align__(16) __half g_wth[(size_t)4*1024*1024];  // W^T (n-major) fp16

#define SC_ALPHA 0.18033688011112042f   // 0.125 * log2(e)

// ---------------------------------------------------------------------------
// Helpers
// ---------------------------------------------------------------------------
__device__ __forceinline__ uint32_t pack_h2(float lo, float hi) {
    uint32_t r;
    asm("cvt.rn.f16x2.f32 %0, %1, %2;" : "=r"(r) : "f"(hi), "f"(lo));
    return r;
}
__device__ __forceinline__ uint32_t smem_u32(const void* p) {
    return (uint32_t)__cvta_generic_to_shared(p);
}
__device__ __forceinline__ void ldsm4(uint32_t& r0, uint32_t& r1,
                                      uint32_t& r2, uint32_t& r3, uint32_t addr) {
    asm volatile("ldmatrix.sync.aligned.m8n8.x4.shared.b16 {%0,%1,%2,%3}, [%4];"
                 : "=r"(r0), "=r"(r1), "=r"(r2), "=r"(r3) : "r"(addr));
}
__device__ __forceinline__ void mma_f16(float c[4], const uint32_t a[4],
                                        uint32_t b0, uint32_t b1) {
    asm volatile(
        "mma.sync.aligned.m16n8k16.row.col.f32.f16.f16.f32 "
        "{%0,%1,%2,%3}, {%4,%5,%6,%7}, {%8,%9}, {%0,%1,%2,%3};"
        : "+f"(c[0]), "+f"(c[1]), "+f"(c[2]), "+f"(c[3])
        : "r"(a[0]), "r"(a[1]), "r"(a[2]), "r"(a[3]), "r"(b0), "r"(b1));
}
__device__ __forceinline__ void cp16(uint32_t dst, const void* src) {
    asm volatile("cp.async.cg.shared.global [%0], [%1], 16;"
                 :: "r"(dst), "l"(src));
}
__device__ __forceinline__ void cp_commit() {
    asm volatile("cp.async.commit_group;");
}
__device__ __forceinline__ void cp_wait0() {
    asm volatile("cp.async.wait_group 0;" ::: "memory");
}
__device__ __forceinline__ void cp_wait1() {
    asm volatile("cp.async.wait_group 1;" ::: "memory");
}
__device__ __forceinline__ void cp_wait2() {
    asm volatile("cp.async.wait_group 2;" ::: "memory");
}

// ---------------------------------------------------------------------------
// Prep: x -> fp16 ; W -> W^T fp16
// ---------------------------------------------------------------------------
__global__ void prep_x(const float* __restrict__ x)
{
    size_t i8 = blockIdx.x * 256 + threadIdx.x;
    const float4* xp = (const float4*)x;
    float4 v0 = xp[i8 * 2], v1 = xp[i8 * 2 + 1];
    uint4 o;
    o.x = pack_h2(v0.x, v0.y);
    o.y = pack_h2(v0.z, v0.w);
    o.z = pack_h2(v1.x, v1.y);
    o.w = pack_h2(v1.z, v1.w);
    ((uint4*)g_xh)[i8] = o;
}

__global__ void prep_wt(const float* __restrict__ wq,
                        const float* __restrict__ wk,
                        const float* __restrict__ wv,
                        const float* __restrict__ wo)
{
    __shared__ float tile[32][33];
    const int z = blockIdx.z;
    const float* W = (z == 0) ? wq : (z == 1) ? wk : (z == 2) ? wv : wo;
    const int k0 = blockIdx.y * 32;
    const int n0 = blockIdx.x * 32;
    const int t = threadIdx.x;
    const int r = t >> 3;
    const int c4 = (t & 7) * 4;

    float4 v = *(const float4*)&W[(size_t)(k0 + r) * 1024 + n0 + c4];
    tile[r][c4 + 0] = v.x;
    tile[r][c4 + 1] = v.y;
    tile[r][c4 + 2] = v.z;
    tile[r][c4 + 3] = v.w;
    __syncthreads();
    uint2 o;
    o.x = pack_h2(tile[c4 + 0][r], tile[c4 + 1][r]);
    o.y = pack_h2(tile[c4 + 2][r], tile[c4 + 3][r]);
    *(uint2*)&g_wth[(size_t)z * 1048576 + (size_t)(n0 + r) * 1024 + k0 + c4] = o;
}

// ---------------------------------------------------------------------------
// fp16 legacy-HMMA GEMM: C[M,1024] = A * W.
// Block tile 128(M) x 128(N), K-tile 32, 3-stage cp.async.
// 128 threads = 4 warps (2M x 2N), warp tile 64x64 -> 2 CTAs/SM.
// Rows padded to 40 halfs (80B = 5*16B -> ldmatrix conflict-free).
// MODE 0: A=g_xh, z->(Wq,Wk,Wv); q scaled by SC_ALPHA; v stored [B,H,P,T].
// MODE 1: A=g_yh, W=Wo, C=d_out f32.
// ---------------------------------------------------------------------------
#define GLDH 40
#define AS_H (128*GLDH)            // 5120 halfs
#define BS_H (128*GLDH)            // 5120 halfs
#define STAGE_H (AS_H + BS_H)      // 10240 halfs = 20480 B
#define GEMM_SMEM_BYTES (3*STAGE_H*2)   // 61440; x2 CTAs = 122880

template <int MODE>
__global__ __launch_bounds__(128, 2)
void gemm_tc(float* __restrict__ outp)
{
    extern __shared__ __half sm_g[];
    const int m0 = blockIdx.y * 128;
    const int n0 = blockIdx.x * 128;
    const int z  = (MODE == 0) ? blockIdx.z : 3;

    const __half* Ap = (MODE == 0) ? g_xh : g_yh;
    const __half* Wt = g_wth + (size_t)z * 1048576;
    __half* Cq = nullptr;
    if (MODE == 0) Cq = (z == 0) ? g_qh : ((z == 1) ? g_kh : g_vh);

    const int tid  = threadIdx.x;
    const int lane = tid & 31;
    const int warp = tid >> 5;
    const int wm = (warp >> 1) * 64;
    const int wn = (warp & 1) * 64;
    const int gid = lane >> 2;
    const int tig = lane & 3;

    const int aRow = lane & 15;
    const uint32_t aHi = (uint32_t)(lane >> 4) * 16u;
    const int bRowRel = (lane & 7) + ((lane >> 4) << 3);
    const uint32_t bHi = (uint32_t)((lane >> 3) & 1) * 16u;

    const uint32_t smBase = smem_u32(sm_g);
    uint32_t aOff[4], bOff[4];
#pragma unroll
    for (int mf = 0; mf < 4; mf++)
        aOff[mf] = (uint32_t)((wm + mf * 16 + aRow) * GLDH) * 2u + aHi;
#pragma unroll
    for (int nfp = 0; nfp < 4; nfp++)
        bOff[nfp] = (uint32_t)((wn + nfp * 16 + bRowRel) * GLDH) * 2u + bHi
                    + (uint32_t)AS_H * 2u;

    float acc[4][8][4];
#pragma unroll
    for (int mf = 0; mf < 4; mf++)
#pragma unroll
        for (int nf = 0; nf < 8; nf++)
#pragma unroll
            for (int i = 0; i < 4; i++) acc[mf][nf][i] = 0.f;

    auto cpStage = [&](int kt, int s) {
        uint32_t As = smBase + (uint32_t)(s * STAGE_H) * 2u;
        uint32_t Bs = As + (uint32_t)AS_H * 2u;
#pragma unroll
        for (int r = 0; r < 4; r++) {          // A: 128 rows x 4 chunks
            int lin = tid + r * 128;
            int row = lin >> 2;
            int ck  = lin & 3;
            cp16(As + (uint32_t)(row * GLDH + ck * 8) * 2u,
                 Ap + (size_t)(m0 + row) * 1024 + kt * 32 + ck * 8);
        }
#pragma unroll
        for (int r = 0; r < 4; r++) {          // B: 128 rows x 4 chunks
            int lin = tid + r * 128;
            int row = lin >> 2;
            int ck  = lin & 3;
            cp16(Bs + (uint32_t)(row * GLDH + ck * 8) * 2u,
                 Wt + (size_t)(n0 + row) * 1024 + kt * 32 + ck * 8);
        }
        cp_commit();
    };

    cpStage(0, 0);
    cpStage(1, 1);
    cpStage(2, 2);

    for (int kt = 0; kt < 32; kt++) {
        if (kt < 30) cp_wait2(); else if (kt == 30) cp_wait1(); else cp_wait0();
        __syncthreads();

        const uint32_t stB = smBase + (uint32_t)((kt % 3) * STAGE_H) * 2u;
#pragma unroll
        for (int kf = 0; kf < 2; kf++) {
            uint32_t a[4][4];
#pragma unroll
            for (int mf = 0; mf < 4; mf++)
                ldsm4(a[mf][0], a[mf][1], a[mf][2], a[mf][3],
                      stB + aOff[mf] + (uint32_t)(kf * 32));
            uint32_t b[8][2];
#pragma unroll
            for (int nfp = 0; nfp < 4; nfp++)
                ldsm4(b[2*nfp][0], b[2*nfp][1], b[2*nfp+1][0], b[2*nfp+1][1],
                      stB + bOff[nfp] + (uint32_t)(kf * 32));
#pragma unroll
            for (int mf = 0; mf < 4; mf++)
#pragma unroll
                for (int nf = 0; nf < 8; nf++)
                    mma_f16(acc[mf][nf], a[mf], b[nf][0], b[nf][1]);
        }

        __syncthreads();
        if (kt + 3 < 32) cpStage(kt + 3, kt % 3);
    }

    // Epilogue
    const float s = (MODE == 0 && z == 0) ? SC_ALPHA : 1.0f;
#pragma unroll
    for (int mf = 0; mf < 4; mf++) {
#pragma unroll
        for (int nf = 0; nf < 8; nf++) {
            int row = m0 + wm + mf * 16 + gid;
            int col = n0 + wn + nf * 8 + tig * 2;
#pragma unroll
            for (int half = 0; half < 2; half++) {
                int rr = row + half * 8;
                float v0 = acc[mf][nf][half * 2];
                float v1 = acc[mf][nf][half * 2 + 1];
                if (MODE == 0) {
                    int b = rr >> 11;
                    int t = rr & 2047;
                    int h = col >> 6;
                    int p = col & 63;
                    if (z == 2) {
                        size_t o = (((size_t)(b * H_ + h) * P_ + p) * T_ + t);
                        Cq[o]      = __float2half_rn(v0);
                        Cq[o + T_] = __float2half_rn(v1);
                    } else {
                        *(uint32_t*)&Cq[(((size_t)(b * H_ + h) * T_ + t) * P_ + p)] =
                            pack_h2(v0 * s, v1 * s);
                    }
                } else {
                    *(float2*)&outp[(size_t)rr * 1024 + col] = make_float2(v0, v1);
                }
            }
        }
    }
}

// ---------------------------------------------------------------------------
// fp16 tensor-core flash attention, causal.
// 128 thr = 4 warps x 32 q-rows; kv tiles 64 double-buffered; occ 2;
// register-resident P. Q pre-scaled by SC_ALPHA -> exp2f without multiply.
// ---------------------------------------------------------------------------
#define LDH 72
#define QS_H (128*LDH)
#define KS_H (64*LDH)
#define OFF_K0 QS_H
#define OFF_K1 (QS_H + KS_H)
#define OFF_V0 (QS_H + 2*KS_H)
#define OFF_V1 (QS_H + 3*KS_H)
#define ATTN_SMEM_BYTES ((QS_H + 4*KS_H)*2)    // 55296; x2 CTAs

__global__ __launch_bounds__(128, 2)
void attn_tc()
{
    extern __shared__ __half sm[];

    const int bh = blockIdx.y;
    const int b  = bh >> 4;
    const int h  = bh & 15;
    const int qt = (int)gridDim.x - 1 - (int)blockIdx.x;  // heavy blocks first
    const int q0 = qt * 128;

    const size_t base = (size_t)bh * T_ * P_;
    const __half* Qp  = g_qh + base;
    const __half* Kp  = g_kh + base;
    const __half* VpT = g_vh + base;

    const int tid  = threadIdx.x;
    const int lane = tid & 31;
    const int warp = tid >> 5;
    const int gid  = lane >> 2;
    const int tig  = lane & 3;
    const int aRow = lane & 15;
    const uint32_t aHi = (uint32_t)(lane >> 4) * 16u;
    const int bRowRel = (lane & 7) + ((lane >> 4) << 3);
    const uint32_t bHi = (uint32_t)((lane >> 3) & 1) * 16u;

    const uint32_t smBase = smem_u32(sm);
    const uint32_t QsB = smBase;
    const uint32_t KsB[2] = { smBase + OFF_K0 * 2, smBase + OFF_K1 * 2 };
    const uint32_t VtB[2] = { smBase + OFF_V0 * 2, smBase + OFF_V1 * 2 };

    const int wm = warp * 32;
    uint32_t qOff[2], bOffR[4];
#pragma unroll
    for (int mf = 0; mf < 2; mf++)
        qOff[mf] = (uint32_t)((wm + mf * 16 + aRow) * LDH) * 2u + aHi;
#pragma unroll
    for (int nfp = 0; nfp < 4; nfp++)
        bOffR[nfp] = (uint32_t)((nfp * 16 + bRowRel) * LDH) * 2u + bHi;

#pragma unroll
    for (int r = 0; r < 8; r++) {
        int it = tid + r * 128;
        int rw = it >> 3;
        int ck = it & 7;
        cp16(QsB + (uint32_t)(rw * LDH + ck * 8) * 2u,
             Qp + (size_t)(q0 + rw) * 64 + ck * 8);
    }
    cp_commit();

    const int ntiles = 2 * qt + 2;
    const int nt_w = 2 * qt + 1 + (warp >> 1);

    auto loadKV = [&](int jt, int buf) {
        const int j0 = jt * 64;
#pragma unroll
        for (int r = 0; r < 4; r++) {
            int it = tid + r * 128;
            int rw = it >> 3;
            int ck = it & 7;
            cp16(KsB[buf] + (uint32_t)(rw * LDH + ck * 8) * 2u,
                 Kp + (size_t)(j0 + rw) * 64 + ck * 8);
        }
#pragma unroll
        for (int r = 0; r < 4; r++) {
            int it = tid + r * 128;
            int d  = it >> 3;
            int tc = it & 7;
            cp16(VtB[buf] + (uint32_t)(d * LDH + tc * 8) * 2u,
                 VpT + (size_t)d * T_ + j0 + tc * 8);
        }
        cp_commit();
    };

    loadKV(0, 0);
    loadKV(1, 1);

    float accO[2][8][4];
#pragma unroll
    for (int mf = 0; mf < 2; mf++)
#pragma unroll
        for (int nf = 0; nf < 8; nf++)
#pragma unroll
            for (int i = 0; i < 4; i++) accO[mf][nf][i] = 0.f;
    float mr[2][2] = {{-INFINITY, -INFINITY}, {-INFINITY, -INFINITY}};
    float ll[2][2] = {{0.f, 0.f}, {0.f, 0.f}};

    for (int jt = 0; jt < ntiles; jt++) {
        if (jt + 2 < ntiles) cp_wait1(); else cp_wait0();
        __syncthreads();

        if (jt < nt_w) {
            const int buf = jt & 1;
            const int j0  = jt * 64;

            float c[2][8][4];
#pragma unroll
            for (int mf = 0; mf < 2; mf++)
#pragma unroll
                for (int nf = 0; nf < 8; nf++)
#pragma unroll
                    for (int i = 0; i < 4; i++) c[mf][nf][i] = 0.f;

#pragma unroll
            for (int kf = 0; kf < 4; kf++) {
                uint32_t a[2][4];
#pragma unroll
                for (int mf = 0; mf < 2; mf++)
                    ldsm4(a[mf][0], a[mf][1], a[mf][2], a[mf][3],
                          QsB + qOff[mf] + (uint32_t)(kf * 32));
#pragma unroll
                for (int nfp = 0; nfp < 4; nfp++) {
                    uint32_t b0, b1, b2, b3;
                    ldsm4(b0, b1, b2, b3,
                          KsB[buf] + bOffR[nfp] + (uint32_t)(kf * 32));
#pragma unroll
                    for (int mf = 0; mf < 2; mf++) {
                        mma_f16(c[mf][2 * nfp],     a[mf], b0, b1);
                        mma_f16(c[mf][2 * nfp + 1], a[mf], b2, b3);
                    }
                }
            }

            if (jt == nt_w - 1) {
#pragma unroll
                for (int mf = 0; mf < 2; mf++) {
                    int row0 = q0 + wm + mf * 16 + gid;
#pragma unroll
                    for (int nf = 0; nf < 8; nf++) {
                        int col = j0 + nf * 8 + tig * 2;
                        if (col     > row0)     c[mf][nf][0] = -INFINITY;
                        if (col + 1 > row0)     c[mf][nf][1] = -INFINITY;
                        if (col     > row0 + 8) c[mf][nf][2] = -INFINITY;
                        if (col + 1 > row0 + 8) c[mf][nf][3] = -INFINITY;
                    }
                }
            }

#pragma unroll
            for (int mf = 0; mf < 2; mf++) {
                float rm0 = -INFINITY, rm1 = -INFINITY;
#pragma unroll
                for (int nf = 0; nf < 8; nf++) {
                    rm0 = fmaxf(rm0, fmaxf(c[mf][nf][0], c[mf][nf][1]));
                    rm1 = fmaxf(rm1, fmaxf(c[mf][nf][2], c[mf][nf][3]));
                }
#pragma unroll
                for (int off = 1; off < 4; off <<= 1) {
                    rm0 = fmaxf(rm0, __shfl_xor_sync(0xffffffffu, rm0, off));
                    rm1 = fmaxf(rm1, __shfl_xor_sync(0xffffffffu, rm1, off));
                }
                float mn0 = fmaxf(mr[mf][0], rm0);
                float mn1 = fmaxf(mr[mf][1], rm1);
                float al0 = exp2f(mr[mf][0] - mn0);
                float al1 = exp2f(mr[mf][1] - mn1);
                float rs0 = 0.f, rs1 = 0.f;
#pragma unroll
                for (int nf = 0; nf < 8; nf++) {
                    c[mf][nf][0] = exp2f(c[mf][nf][0] - mn0);
                    c[mf][nf][1] = exp2f(c[mf][nf][1] - mn0);
                    c[mf][nf][2] = exp2f(c[mf][nf][2] - mn1);
                    c[mf][nf][3] = exp2f(c[mf][nf][3] - mn1);
                    rs0 += c[mf][nf][0] + c[mf][nf][1];
                    rs1 += c[mf][nf][2] + c[mf][nf][3];
                }
#pragma unroll
                for (int off = 1; off < 4; off <<= 1) {
                    rs0 += __shfl_xor_sync(0xffffffffu, rs0, off);
                    rs1 += __shfl_xor_sync(0xffffffffu, rs1, off);
                }
                ll[mf][0] = ll[mf][0] * al0 + rs0;
                ll[mf][1] = ll[mf][1] * al1 + rs1;
                mr[mf][0] = mn0;
                mr[mf][1] = mn1;
#pragma unroll
                for (int nf = 0; nf < 8; nf++) {
                    accO[mf][nf][0] *= al0;
                    accO[mf][nf][1] *= al0;
                    accO[mf][nf][2] *= al1;
                    accO[mf][nf][3] *= al1;
                }
            }

#pragma unroll
            for (int kf = 0; kf < 4; kf++) {
                uint32_t pa[2][4];
#pragma unroll
                for (int mf = 0; mf < 2; mf++) {
                    pa[mf][0] = pack_h2(c[mf][2*kf][0],   c[mf][2*kf][1]);
                    pa[mf][1] = pack_h2(c[mf][2*kf][2],   c[mf][2*kf][3]);
                    pa[mf][2] = pack_h2(c[mf][2*kf+1][0], c[mf][2*kf+1][1]);
                    pa[mf][3] = pack_h2(c[mf][2*kf+1][2], c[mf][2*kf+1][3]);
                }
#pragma unroll
                for (int nfp = 0; nfp < 4; nfp++) {
                    uint32_t b0, b1, b2, b3;
                    ldsm4(b0, b1, b2, b3,
                          VtB[buf] + bOffR[nfp] + (uint32_t)(kf * 32));
#pragma unroll
                    for (int mf = 0; mf < 2; mf++) {
                        mma_f16(accO[mf][2 * nfp],     pa[mf], b0, b1);
                        mma_f16(accO[mf][2 * nfp + 1], pa[mf], b2, b3);
                    }
                }
            }
        }

        __syncthreads();
        if (jt + 2 < ntiles) loadKV(jt + 2, jt & 1);
    }

#pragma unroll
    for (int mf = 0; mf < 2; mf++) {
        float inv0 = 1.f / ll[mf][0];
        float inv1 = 1.f / ll[mf][1];
        int rowg = q0 + wm + mf * 16 + gid;
        __half* y0 = g_yh + ((size_t)(b * T_ + rowg)) * D_ + h * 64 + tig * 2;
        __half* y1 = y0 + 8 * (size_t)D_;
#pragma unroll
        for (int nf = 0; nf < 8; nf++) {
            *(uint32_t*)&y0[nf * 8] = pack_h2(accO[mf][nf][0] * inv0,
                                              accO[mf][nf][1] * inv0);
            *(uint32_t*)&y1[nf * 8] = pack_h2(accO[mf][nf][2] * inv1,
                                              accO[mf][nf][3] * inv1);
        }
    }
}

// ---------------------------------------------------------------------------
extern "C" void kernel_launch(void* const* d_in, const int* in_sizes, int n_in,
                              void* d_out, int out_size)
{
    const float* x  = (const float*)d_in[0];
    const float* Wq = (const float*)d_in[2];
    const float* Wk = (const float*)d_in[3];
    const float* Wv = (const float*)d_in[4];
    const float* Wo = (const float*)d_in[5];
    float* out = (float*)d_out;

    cudaFuncSetAttribute(gemm_tc<0>, cudaFuncAttributeMaxDynamicSharedMemorySize,
                         GEMM_SMEM_BYTES);
    cudaFuncSetAttribute(gemm_tc<1>, cudaFuncAttributeMaxDynamicSharedMemorySize,
                         GEMM_SMEM_BYTES);
    cudaFuncSetAttribute(attn_tc, cudaFuncAttributeMaxDynamicSharedMemorySize,
                         ATTN_SMEM_BYTES);

    prep_x<<<4096, 256>>>(x);
    prep_wt<<<dim3(32, 32, 4), 256>>>(Wq, Wk, Wv, Wo);

    // QKV projections (q pre-scaled, v transposed); 128x128 blocks, 2 CTAs/SM
    gemm_tc<0><<<dim3(8, 64, 3), 128, GEMM_SMEM_BYTES>>>(nullptr);

    // Flash attention
    attn_tc<<<dim3(T_/128, B_*H_), 128, ATTN_SMEM_BYTES>>>();

    // Output projection
    gemm_tc<1><<<dim3(8, 64, 1), 128, GEMM_SMEM_BYTES>>>(out);
}